// round 12
// baseline (speedup 1.0000x reference)
#include <cuda_runtime.h>
#include <cuda_bf16.h>
#include <cstdint>

#define N_NODES 51200
#define N_EDGES 614400
#define ORIG    92
#define AFL     64
#define BINS    100
#define NCONV   3
#define TBL     128
#define FCO     128      // 2*AFL
#define EPS_BN  1e-5f
#define EGRID   1024
#define DGRID   1024
#define PROJ_ROWS 64
#define HPAD    68
#define PB      64
#define HT_PAD  68
#define KC      32

typedef unsigned long long u64;
__device__ __forceinline__ u64 pack2(float lo, float hi) {
    u64 r; asm("mov.b64 %0, {%1, %2};" : "=l"(r) : "f"(lo), "f"(hi)); return r;
}
__device__ __forceinline__ void unpack2(u64 v, float& lo, float& hi) {
    asm("mov.b64 {%0, %1}, %2;" : "=f"(lo), "=f"(hi) : "l"(v));
}
__device__ __forceinline__ u64 fma2(u64 a, u64 b, u64 c) {
    u64 d; asm("fma.rn.f32x2 %0, %1, %2, %3;" : "=l"(d) : "l"(a), "l"(b), "l"(c));
    return d;
}

// ---------------- device scratch (static, no allocations) ----------------
__device__ float g_h[N_NODES * AFL];
__device__ float g_Zd[N_NODES * FCO];
__device__ float g_Zs[N_NODES * FCO];
__device__ float g_T[TBL * FCO];
__device__ float g_aggr[N_NODES * AFL];
__device__ float g_part1[EGRID * 256];
__device__ float g_part2[DGRID * 128];
__device__ float g_bn1sc[FCO], g_bn1sh[FCO];
__device__ float g_bn2sc[AFL], g_bn2sh[AFL];
__device__ int   g_cnt[N_NODES];              // zero-init; re-zeroed by k_scan
__device__ int   g_segstart[N_NODES + 1];
__device__ int   g_off[N_NODES];
__device__ int   g_psrc[N_EDGES];
__device__ int   g_pdst[N_EDGES];
__device__ float g_pattr[N_EDGES];

// ---------------- edge sort ----------------
__global__ void __launch_bounds__(1024) k_hist(const int* __restrict__ ei,
                                               float* __restrict__ out, int osz) {
    int e = blockIdx.x * blockDim.x + threadIdx.x;
    if (e < osz) out[e] = 0.f;
    if (e < N_EDGES) atomicAdd(&g_cnt[ei[N_EDGES + e]], 1);
}

__global__ void __launch_bounds__(1024) k_scan() {
    __shared__ int wsum[32];
    __shared__ int carry;
    int tid = threadIdx.x;
    int lane = tid & 31, wid = tid >> 5;
    if (tid == 0) carry = 0;
    __syncthreads();
    for (int base = 0; base < N_NODES; base += 1024) {
        int v = g_cnt[base + tid];
        g_cnt[base + tid] = 0;
        int x = v;
#pragma unroll
        for (int o = 1; o < 32; o <<= 1) {
            int t = __shfl_up_sync(0xffffffffu, x, o);
            if (lane >= o) x += t;
        }
        if (lane == 31) wsum[wid] = x;
        __syncthreads();
        if (wid == 0) {
            int sv = wsum[lane];
#pragma unroll
            for (int o = 1; o < 32; o <<= 1) {
                int t = __shfl_up_sync(0xffffffffu, sv, o);
                if (lane >= o) sv += t;
            }
            wsum[lane] = sv;
        }
        __syncthreads();
        int woff = (wid > 0) ? wsum[wid - 1] : 0;
        int ex = carry + woff + x - v;
        g_segstart[base + tid] = ex;
        g_off[base + tid] = ex;
        __syncthreads();
        if (tid == 0) carry += wsum[31];
        __syncthreads();
    }
    if (tid == 0) g_segstart[N_NODES] = N_EDGES;
}

__global__ void __launch_bounds__(1024) k_scatter(const int* __restrict__ ei,
                                                  const float* __restrict__ ea) {
    int e = blockIdx.x * blockDim.x + threadIdx.x;
    if (e < N_EDGES) {
        int dst = ei[N_EDGES + e];
        int pos = atomicAdd(&g_off[dst], 1);
        g_psrc[pos] = ei[e];
        g_pdst[pos] = dst;
        g_pattr[pos] = ea[e];
    }
}

// ---------------- shared pool helper ----------------
__device__ __forceinline__ void pool_tile(
    const float* __restrict__ ppWs, const float* __restrict__ hsT,
    float* __restrict__ red, const float* __restrict__ ppb,
    float* __restrict__ out, int n0, int numAtom, int tx, int ty, int tid)
{
    const float4* W4 = reinterpret_cast<const float4*>(ppWs);
    const float4* H4 = reinterpret_cast<const float4*>(hsT);
    float4 pb = *reinterpret_cast<const float4*>(ppb + 4 * tx);
    float4 p0 = pb, p1 = pb, p2 = pb, p3 = pb;
#pragma unroll 8
    for (int k = 0; k < AFL; k++) {
        float4 w4 = W4[k * 16 + tx];
        float4 h4 = H4[k * (HT_PAD / 4) + ty];
        p0.x = fmaf(h4.x, w4.x, p0.x); p0.y = fmaf(h4.x, w4.y, p0.y);
        p0.z = fmaf(h4.x, w4.z, p0.z); p0.w = fmaf(h4.x, w4.w, p0.w);
        p1.x = fmaf(h4.y, w4.x, p1.x); p1.y = fmaf(h4.y, w4.y, p1.y);
        p1.z = fmaf(h4.y, w4.z, p1.z); p1.w = fmaf(h4.y, w4.w, p1.w);
        p2.x = fmaf(h4.z, w4.x, p2.x); p2.y = fmaf(h4.z, w4.y, p2.y);
        p2.z = fmaf(h4.z, w4.z, p2.z); p2.w = fmaf(h4.z, w4.w, p2.w);
        p3.x = fmaf(h4.w, w4.x, p3.x); p3.y = fmaf(h4.w, w4.y, p3.y);
        p3.z = fmaf(h4.w, w4.z, p3.z); p3.w = fmaf(h4.w, w4.w, p3.w);
    }
    float4 pv[4] = {p0, p1, p2, p3};
    float4 val[4];
#pragma unroll
    for (int i = 0; i < 4; i++) {
        float4 p = pv[i];
        float m = fmaxf(fmaxf(p.x, p.y), fmaxf(p.z, p.w));
#pragma unroll
        for (int o = 1; o < 16; o <<= 1)
            m = fmaxf(m, __shfl_xor_sync(0xffffffffu, m, o));
        float4 e;
        e.x = expf(p.x - m); e.y = expf(p.y - m);
        e.z = expf(p.z - m); e.w = expf(p.w - m);
        float s = (e.x + e.y) + (e.z + e.w);
#pragma unroll
        for (int o = 1; o < 16; o <<= 1)
            s += __shfl_xor_sync(0xffffffffu, s, o);
        float inv = 1.f / s;
        val[i] = make_float4(e.x * inv, e.y * inv, e.z * inv, e.w * inv);
    }
    bool same = (n0 / numAtom) == ((n0 + PB - 1) / numAtom);
    if (same) {
        float4 cs;
        cs.x = (val[0].x + val[1].x) + (val[2].x + val[3].x);
        cs.y = (val[0].y + val[1].y) + (val[2].y + val[3].y);
        cs.z = (val[0].z + val[1].z) + (val[2].z + val[3].z);
        cs.w = (val[0].w + val[1].w) + (val[2].w + val[3].w);
        *reinterpret_cast<float4*>(&red[ty * 64 + 4 * tx]) = cs;
        __syncthreads();
        if (tid < 64) {
            float s = 0.f;
#pragma unroll
            for (int r = 0; r < 16; r++) s += red[r * 64 + tid];
            atomicAdd(&out[(n0 / numAtom) * AFL + tid], s);
        }
    } else {
#pragma unroll
        for (int i = 0; i < 4; i++) {
            int node = n0 + 4 * ty + i;
            int cry = node / numAtom;
            atomicAdd(&out[cry * AFL + 4 * tx + 0], val[i].x);
            atomicAdd(&out[cry * AFL + 4 * tx + 1], val[i].y);
            atomicAdd(&out[cry * AFL + 4 * tx + 2], val[i].z);
            atomicAdd(&out[cry * AFL + 4 * tx + 3], val[i].w);
        }
    }
}

// ---------------- embedding + initial pooling ----------------
__global__ void __launch_bounds__(256) k_embed_pool(
    const float* __restrict__ x, const float* __restrict__ att,
    const float* __restrict__ W, const float* __restrict__ b,
    const float* __restrict__ ppW, const float* __restrict__ ppb,
    float* __restrict__ out, const int* __restrict__ bs)
{
    __shared__ float sbuf[KC * AFL + KC * HT_PAD];
    __shared__ float hsT[AFL * HT_PAD];
    __shared__ float red[16 * AFL];
    float* Wc = sbuf;
    float* xsT = sbuf + KC * AFL;
    int tid = threadIdx.x;
    int tx = tid & 15, ty = tid >> 4;
    int n0 = blockIdx.x * PB;

    float4 b4 = *reinterpret_cast<const float4*>(b + 4 * tx);
    float4 a0 = b4, a1 = b4, a2 = b4, a3 = b4;

    for (int kc = 0; kc < ORIG; kc += KC) {
        int kl = min(KC, ORIG - kc);
        __syncthreads();
        for (int i = tid; i < kl * AFL; i += 256) Wc[i] = W[kc * AFL + i];
        for (int idx = tid; idx < PB * KC; idx += 256) {
            int n = idx >> 5, k = idx & 31;
            if (k < kl)
                xsT[k * HT_PAD + n] = x[(size_t)(n0 + n) * ORIG + kc + k] * att[kc + k];
        }
        __syncthreads();
        const float4* Wc4 = reinterpret_cast<const float4*>(Wc);
        const float4* X4 = reinterpret_cast<const float4*>(xsT);
#pragma unroll 4
        for (int k = 0; k < kl; k++) {
            float4 w4 = Wc4[k * 16 + tx];
            float4 h4 = X4[k * (HT_PAD / 4) + ty];
            a0.x = fmaf(h4.x, w4.x, a0.x); a0.y = fmaf(h4.x, w4.y, a0.y);
            a0.z = fmaf(h4.x, w4.z, a0.z); a0.w = fmaf(h4.x, w4.w, a0.w);
            a1.x = fmaf(h4.y, w4.x, a1.x); a1.y = fmaf(h4.y, w4.y, a1.y);
            a1.z = fmaf(h4.y, w4.z, a1.z); a1.w = fmaf(h4.y, w4.w, a1.w);
            a2.x = fmaf(h4.z, w4.x, a2.x); a2.y = fmaf(h4.z, w4.y, a2.y);
            a2.z = fmaf(h4.z, w4.z, a2.z); a2.w = fmaf(h4.z, w4.w, a2.w);
            a3.x = fmaf(h4.w, w4.x, a3.x); a3.y = fmaf(h4.w, w4.y, a3.y);
            a3.z = fmaf(h4.w, w4.z, a3.z); a3.w = fmaf(h4.w, w4.w, a3.w);
        }
    }
    float4 av[4] = {a0, a1, a2, a3};
#pragma unroll
    for (int i = 0; i < 4; i++) {
        int node = n0 + 4 * ty + i;
        *reinterpret_cast<float4*>(&g_h[(size_t)node * AFL + 4 * tx]) = av[i];
        hsT[(4 * tx + 0) * HT_PAD + 4 * ty + i] = av[i].x;
        hsT[(4 * tx + 1) * HT_PAD + 4 * ty + i] = av[i].y;
        hsT[(4 * tx + 2) * HT_PAD + 4 * ty + i] = av[i].z;
        hsT[(4 * tx + 3) * HT_PAD + 4 * ty + i] = av[i].w;
    }
    __syncthreads();
    for (int i = tid; i < AFL * AFL; i += 256) sbuf[i] = ppW[i];
    __syncthreads();
    int numAtom = N_NODES / bs[0];
    pool_tile(sbuf, hsT, red, ppb, out, n0, numAtom, tx, ty, tid);
}

// ---------------- update + pooling ----------------
__global__ void __launch_bounds__(256) k_update_pool(
    const float* __restrict__ ppW, const float* __restrict__ ppb,
    float* __restrict__ out, const int* __restrict__ bs)
{
    __shared__ float ppWs[AFL * AFL];
    __shared__ float hsT[AFL * HT_PAD];
    __shared__ float red[16 * AFL];
    int tid = threadIdx.x;
    int tx = tid & 15, ty = tid >> 4;
    int n0 = blockIdx.x * PB;

    for (int i = tid; i < AFL * AFL; i += 256) ppWs[i] = ppW[i];
    for (int idx = tid; idx < PB * 16; idx += 256) {
        int n = idx >> 4, c4 = idx & 15;
        size_t base = (size_t)(n0 + n) * AFL + 4 * c4;
        float4 h4 = *reinterpret_cast<const float4*>(&g_h[base]);
        float4 g4 = *reinterpret_cast<const float4*>(&g_aggr[base]);
        float4 sc = reinterpret_cast<const float4*>(g_bn2sc)[c4];
        float4 sh = reinterpret_cast<const float4*>(g_bn2sh)[c4];
        float4 up;
        up.x = fmaxf(h4.x + fmaf(g4.x, sc.x, sh.x), 0.f);
        up.y = fmaxf(h4.y + fmaf(g4.y, sc.y, sh.y), 0.f);
        up.z = fmaxf(h4.z + fmaf(g4.z, sc.z, sh.z), 0.f);
        up.w = fmaxf(h4.w + fmaf(g4.w, sc.w, sh.w), 0.f);
        *reinterpret_cast<float4*>(&g_h[base]) = up;
        hsT[(4 * c4 + 0) * HT_PAD + n] = up.x;
        hsT[(4 * c4 + 1) * HT_PAD + n] = up.y;
        hsT[(4 * c4 + 2) * HT_PAD + n] = up.z;
        hsT[(4 * c4 + 3) * HT_PAD + n] = up.w;
    }
    __syncthreads();
    int numAtom = N_NODES / bs[0];
    pool_tile(ppWs, hsT, red, ppb, out, n0, numAtom, tx, ty, tid);
}

// ---------------- fused table ----------------
__global__ void __launch_bounds__(FCO) k_table(
    const float* __restrict__ w1, const float* __restrict__ b1,
    const float* __restrict__ w2, const float* __restrict__ b2,
    const float* __restrict__ alpha, const float* __restrict__ lut,
    const float* __restrict__ fcW, const float* __restrict__ fcb)
{
    __shared__ float v2[BINS];
    __shared__ float p[BINS];
    __shared__ float q[AFL];
    __shared__ float redA[4];
    __shared__ float redB[4];
    int tid = threadIdx.x;
    float a = (float)blockIdx.x / (float)(TBL - 1);
    if (tid < BINS) {
        float v = fmaf(a, w1[tid], b1[tid]);
        v2[tid] = v > 0.f ? v : 0.01f * v;
    }
    __syncthreads();
    float v3 = -3.0e38f;
    if (tid < BINS) {
        float acc = fmaf(alpha[0], v2[tid], b2[tid]);
#pragma unroll 4
        for (int k = 0; k < BINS; k++) acc = fmaf(v2[k], w2[k * BINS + tid], acc);
        v3 = acc;
    }
    float m = v3;
#pragma unroll
    for (int o = 16; o; o >>= 1) m = fmaxf(m, __shfl_xor_sync(0xffffffffu, m, o));
    if ((tid & 31) == 0) redA[tid >> 5] = m;
    __syncthreads();
    m = fmaxf(fmaxf(redA[0], redA[1]), fmaxf(redA[2], redA[3]));
    float ex = (tid < BINS) ? expf(v3 - m) : 0.f;
    float s = ex;
#pragma unroll
    for (int o = 16; o; o >>= 1) s += __shfl_xor_sync(0xffffffffu, s, o);
    if ((tid & 31) == 0) redB[tid >> 5] = s;
    __syncthreads();
    s = (redB[0] + redB[1]) + (redB[2] + redB[3]);
    float inv = 1.f / s;
    if (tid < BINS) p[tid] = ex * inv;
    __syncthreads();
    if (tid < AFL) {
        float acc = 0.f;
#pragma unroll 4
        for (int j = 0; j < BINS; j++) acc = fmaf(p[j], lut[j * AFL + tid], acc);
        q[tid] = acc;
    }
    __syncthreads();
    float acc = fcb[tid];
#pragma unroll 4
    for (int mm = 0; mm < AFL; mm++)
        acc = fmaf(q[mm], fcW[(2 * AFL + mm) * FCO + tid], acc);
    g_T[blockIdx.x * FCO + tid] = acc;
}

// ---------------- node projections: f32x2-packed register tile (R11 best) ----------------
__global__ void __launch_bounds__(256) k_proj(const float* __restrict__ fcW)
{
    __shared__ float Wsh[16 * 256];
    __shared__ float hsh[AFL * HPAD];
    int tid = threadIdx.x;
    int tx = tid & 63;
    int ty = tid >> 6;
    int r0 = blockIdx.x * PROJ_ROWS;
    int col = 4 * tx;

    for (int i = tid; i < PROJ_ROWS * AFL; i += 256) {
        int r = i >> 6, k = i & 63;
        hsh[k * HPAD + r] = g_h[(size_t)(r0 + r) * AFL + k];
    }

    u64 accP[8][4];
    u64 zero = pack2(0.f, 0.f);
#pragma unroll
    for (int p = 0; p < 8; p++)
#pragma unroll
        for (int c = 0; c < 4; c++) accP[p][c] = zero;

    for (int kc = 0; kc < 4; kc++) {
        __syncthreads();
        for (int i = tid; i < 16 * 256; i += 256) {
            int kk = i >> 8;
            int cl = i & 255;
            int h2 = cl >> 7, c2 = cl & 127;
            Wsh[i] = fcW[(size_t)(h2 * AFL + kc * 16 + kk) * FCO + c2];
        }
        __syncthreads();
#pragma unroll
        for (int kk = 0; kk < 16; kk++) {
            float4 w4 = *reinterpret_cast<const float4*>(&Wsh[kk * 256 + col]);
            u64 wd0 = pack2(w4.x, w4.x);
            u64 wd1 = pack2(w4.y, w4.y);
            u64 wd2 = pack2(w4.z, w4.z);
            u64 wd3 = pack2(w4.w, w4.w);
            const u64* hp = reinterpret_cast<const u64*>(
                &hsh[(kc * 16 + kk) * HPAD + ty * 16]);
#pragma unroll
            for (int p = 0; p < 8; p++) {
                u64 h2v = hp[p];
                accP[p][0] = fma2(h2v, wd0, accP[p][0]);
                accP[p][1] = fma2(h2v, wd1, accP[p][1]);
                accP[p][2] = fma2(h2v, wd2, accP[p][2]);
                accP[p][3] = fma2(h2v, wd3, accP[p][3]);
            }
        }
    }
    int half = col >> 7;
    int cc = col & 127;
    float* dst = half ? g_Zs : g_Zd;
#pragma unroll
    for (int p = 0; p < 8; p++) {
        float4 lo4, hi4;
        unpack2(accP[p][0], lo4.x, hi4.x);
        unpack2(accP[p][1], lo4.y, hi4.y);
        unpack2(accP[p][2], lo4.z, hi4.z);
        unpack2(accP[p][3], lo4.w, hi4.w);
        *reinterpret_cast<float4*>(&dst[(size_t)(r0 + ty * 16 + 2 * p) * FCO + cc]) = lo4;
        *reinterpret_cast<float4*>(&dst[(size_t)(r0 + ty * 16 + 2 * p + 1) * FCO + cc]) = hi4;
    }
}

// ---------------- pass C: flat edge-parallel BN1 stats (R8 best) ----------------
__global__ void __launch_bounds__(256) k_edgeC()
{
    __shared__ float sred[8 * 256];
    int tid = threadIdx.x;
    int warp = tid >> 5, lane = tid & 31;
    int gwarp = blockIdx.x * 8 + warp;
    int nwarp = gridDim.x * 8;
    const float4* T4  = reinterpret_cast<const float4*>(g_T);
    const float4* Zd4 = reinterpret_cast<const float4*>(g_Zd);
    const float4* Zs4 = reinterpret_cast<const float4*>(g_Zs);
    float4 ps = {0,0,0,0}, pq = {0,0,0,0};

    for (int e0 = gwarp * 4; e0 < N_EDGES; e0 += nwarp * 4) {
        int4   ss = __ldg(reinterpret_cast<const int4*>(g_psrc + e0));
        int4   dd = __ldg(reinterpret_cast<const int4*>(g_pdst + e0));
        float4 aa = __ldg(reinterpret_cast<const float4*>(g_pattr + e0));
        float4 zs0 = __ldg(Zs4 + (size_t)ss.x * 32 + lane);
        float4 zs1 = __ldg(Zs4 + (size_t)ss.y * 32 + lane);
        float4 zs2 = __ldg(Zs4 + (size_t)ss.z * 32 + lane);
        float4 zs3 = __ldg(Zs4 + (size_t)ss.w * 32 + lane);
        float4 zd0 = __ldg(Zd4 + (size_t)dd.x * 32 + lane);
        float4 zd1 = __ldg(Zd4 + (size_t)dd.y * 32 + lane);
        float4 zd2 = __ldg(Zd4 + (size_t)dd.z * 32 + lane);
        float4 zd3 = __ldg(Zd4 + (size_t)dd.w * 32 + lane);

#define DOEDGE_C(ZD, ZS, A)                                                  \
        {                                                                    \
            float pos = fminf(fmaxf((A) * (float)(TBL - 1), 0.f),            \
                              (float)(TBL - 1));                             \
            int t0 = min((int)pos, TBL - 2);                                 \
            float w = pos - (float)t0;                                       \
            float4 T0 = __ldg(T4 + t0 * 32 + lane);                          \
            float4 T1 = __ldg(T4 + (t0 + 1) * 32 + lane);                    \
            float zx = ZD.x + ZS.x + fmaf(w, T1.x - T0.x, T0.x);             \
            float zy = ZD.y + ZS.y + fmaf(w, T1.y - T0.y, T0.y);             \
            float zz = ZD.z + ZS.z + fmaf(w, T1.z - T0.z, T0.z);             \
            float zw = ZD.w + ZS.w + fmaf(w, T1.w - T0.w, T0.w);             \
            ps.x += zx; ps.y += zy; ps.z += zz; ps.w += zw;                  \
            pq.x = fmaf(zx, zx, pq.x); pq.y = fmaf(zy, zy, pq.y);            \
            pq.z = fmaf(zz, zz, pq.z); pq.w = fmaf(zw, zw, pq.w);            \
        }
        DOEDGE_C(zd0, zs0, aa.x)
        DOEDGE_C(zd1, zs1, aa.y)
        DOEDGE_C(zd2, zs2, aa.z)
        DOEDGE_C(zd3, zs3, aa.w)
#undef DOEDGE_C
    }
    {
        float* sb = &sred[warp * 256];
        int c4 = lane * 4;
        sb[c4 + 0] = ps.x; sb[c4 + 1] = ps.y; sb[c4 + 2] = ps.z; sb[c4 + 3] = ps.w;
        sb[128 + c4 + 0] = pq.x; sb[128 + c4 + 1] = pq.y;
        sb[128 + c4 + 2] = pq.z; sb[128 + c4 + 3] = pq.w;
    }
    __syncthreads();
    float v = 0.f;
#pragma unroll
    for (int w = 0; w < 8; w++) v += sred[w * 256 + tid];
    g_part1[blockIdx.x * 256 + tid] = v;
}

__global__ void __launch_bounds__(256) k_red1(
    const float* __restrict__ g1, const float* __restrict__ b1)
{
    __shared__ float ssum[256], ssq[256];
    int c = blockIdx.x;
    int t = threadIdx.x;
    float s = 0.f, q = 0.f;
    for (int r = t; r < EGRID; r += 256) {
        s += g_part1[r * 256 + c];
        q += g_part1[r * 256 + 128 + c];
    }
    ssum[t] = s; ssq[t] = q;
    __syncthreads();
    for (int o = 128; o; o >>= 1) {
        if (t < o) { ssum[t] += ssum[t + o]; ssq[t] += ssq[t + o]; }
        __syncthreads();
    }
    if (t == 0) {
        const float invE = 1.f / (float)N_EDGES;
        float mu = ssum[0] * invE;
        float var = ssq[0] * invE - mu * mu;
        float sc = rsqrtf(var + EPS_BN) * g1[c];
        g_bn1sc[c] = sc;
        g_bn1sh[c] = fmaf(-mu, sc, b1[c]);
    }
}

// ---------------- pass D: pair-node half-warp, in-lane channel pairing ----------------
// warp = 2 nodes (one per half-warp). lane cl holds channels 4cl..4cl+3 of
// filter (float4 idx cl) AND core (idx 16+cl) -> msg is in-lane, no shuffles.
// 4-wide edge unroll per half-warp => 8 independent zs gathers in flight/warp.
__global__ void __launch_bounds__(256) k_edgeD()
{
    __shared__ float sred[8 * 128];
    int tid = threadIdx.x;
    int warp = tid >> 5, lane = tid & 31;
    int cl = lane & 15, eh = lane >> 4;
    int gw = blockIdx.x * 8 + warp;
    int nw = gridDim.x * 8;
    const float4* T4  = reinterpret_cast<const float4*>(g_T);
    const float4* Zd4 = reinterpret_cast<const float4*>(g_Zd);
    const float4* Zs4 = reinterpret_cast<const float4*>(g_Zs);
    float4 sc0 = reinterpret_cast<const float4*>(g_bn1sc)[cl];
    float4 sc1 = reinterpret_cast<const float4*>(g_bn1sc)[16 + cl];
    float4 sh0 = reinterpret_cast<const float4*>(g_bn1sh)[cl];
    float4 sh1 = reinterpret_cast<const float4*>(g_bn1sh)[16 + cl];
    float4 ps = {0,0,0,0}, pq = {0,0,0,0};
    int srcBase = lane & 16;        // shfl source offset for this half

    for (int n2 = gw * 2; n2 < N_NODES; n2 += nw * 2) {
        int n = n2 + eh;            // this half-warp's node
        int beg = g_segstart[n], end = g_segstart[n + 1];
        float4 zd0 = __ldg(Zd4 + (size_t)n * 32 + cl);
        float4 zd1 = __ldg(Zd4 + (size_t)n * 32 + 16 + cl);
        float4 acc = {0,0,0,0};

        int deg = end - beg;
        int degO = __shfl_xor_sync(0xffffffffu, deg, 16);
        int rounds = (max(deg, degO) + 15) >> 4;     // warp-uniform

        for (int r = 0; r < rounds; r++) {
            int base = beg + r * 16;
            int e = base + cl;
            int sv = 0; float av = 0.f;
            if (e < end) { sv = g_psrc[e]; av = g_pattr[e]; }
            int cnt = max(0, min(16, end - base));   // uniform per half-warp

#pragma unroll
            for (int j = 0; j < 16; j += 4) {
                // warp-uniform early exit: both halves done with this j?
                int mx = max(cnt, __shfl_xor_sync(0xffffffffu, cnt, 16));
                if (j >= mx) break;
                int s0 = __shfl_sync(0xffffffffu, sv, srcBase + j + 0);
                int s1 = __shfl_sync(0xffffffffu, sv, srcBase + j + 1);
                int s2 = __shfl_sync(0xffffffffu, sv, srcBase + j + 2);
                int s3 = __shfl_sync(0xffffffffu, sv, srcBase + j + 3);
                float a0 = __shfl_sync(0xffffffffu, av, srcBase + j + 0);
                float a1 = __shfl_sync(0xffffffffu, av, srcBase + j + 1);
                float a2 = __shfl_sync(0xffffffffu, av, srcBase + j + 2);
                float a3 = __shfl_sync(0xffffffffu, av, srcBase + j + 3);
                const float4* p0 = Zs4 + (size_t)s0 * 32;
                const float4* p1 = Zs4 + (size_t)s1 * 32;
                const float4* p2 = Zs4 + (size_t)s2 * 32;
                const float4* p3 = Zs4 + (size_t)s3 * 32;
                float4 zA0 = __ldg(p0 + cl), zA1 = __ldg(p0 + 16 + cl);
                float4 zB0 = __ldg(p1 + cl), zB1 = __ldg(p1 + 16 + cl);
                float4 zC0 = __ldg(p2 + cl), zC1 = __ldg(p2 + 16 + cl);
                float4 zD0 = __ldg(p3 + cl), zD1 = __ldg(p3 + 16 + cl);

#define DOEDGE_D(ZS0, ZS1, A, JJ)                                            \
                if ((JJ) < cnt) {                                            \
                    float pos = fminf(fmaxf((A) * (float)(TBL - 1), 0.f),    \
                                      (float)(TBL - 1));                     \
                    int t0 = min((int)pos, TBL - 2);                         \
                    float w = pos - (float)t0;                               \
                    float4 T0l = __ldg(T4 + t0 * 32 + cl);                   \
                    float4 T0h = __ldg(T4 + t0 * 32 + 16 + cl);              \
                    float4 T1l = __ldg(T4 + (t0 + 1) * 32 + cl);             \
                    float4 T1h = __ldg(T4 + (t0 + 1) * 32 + 16 + cl);        \
                    float fx = fmaxf(fmaf(zd0.x + ZS0.x + fmaf(w, T1l.x - T0l.x, T0l.x), sc0.x, sh0.x), 0.f); \
                    float fy = fmaxf(fmaf(zd0.y + ZS0.y + fmaf(w, T1l.y - T0l.y, T0l.y), sc0.y, sh0.y), 0.f); \
                    float fz = fmaxf(fmaf(zd0.z + ZS0.z + fmaf(w, T1l.z - T0l.z, T0l.z), sc0.z, sh0.z), 0.f); \
                    float fw = fmaxf(fmaf(zd0.w + ZS0.w + fmaf(w, T1l.w - T0l.w, T0l.w), sc0.w, sh0.w), 0.f); \
                    float gx = fmaxf(fmaf(zd1.x + ZS1.x + fmaf(w, T1h.x - T0h.x, T0h.x), sc1.x, sh1.x), 0.f); \
                    float gy = fmaxf(fmaf(zd1.y + ZS1.y + fmaf(w, T1h.y - T0h.y, T0h.y), sc1.y, sh1.y), 0.f); \
                    float gz = fmaxf(fmaf(zd1.z + ZS1.z + fmaf(w, T1h.z - T0h.z, T0h.z), sc1.z, sh1.z), 0.f); \
                    float gw2 = fmaxf(fmaf(zd1.w + ZS1.w + fmaf(w, T1h.w - T0h.w, T0h.w), sc1.w, sh1.w), 0.f); \
                    acc.x = fmaf(fx, gx, acc.x);                             \
                    acc.y = fmaf(fy, gy, acc.y);                             \
                    acc.z = fmaf(fz, gz, acc.z);                             \
                    acc.w = fmaf(fw, gw2, acc.w);                            \
                }
                DOEDGE_D(zA0, zA1, a0, j + 0)
                DOEDGE_D(zB0, zB1, a1, j + 1)
                DOEDGE_D(zC0, zC1, a2, j + 2)
                DOEDGE_D(zD0, zD1, a3, j + 3)
#undef DOEDGE_D
            }
        }
        // store this node's aggregation (16 lanes per half-warp x float4)
        reinterpret_cast<float4*>(&g_aggr[(size_t)n * AFL])[cl] = acc;
        ps.x += acc.x; ps.y += acc.y; ps.z += acc.z; ps.w += acc.w;
        pq.x = fmaf(acc.x, acc.x, pq.x); pq.y = fmaf(acc.y, acc.y, pq.y);
        pq.z = fmaf(acc.z, acc.z, pq.z); pq.w = fmaf(acc.w, acc.w, pq.w);
    }
    // combine halves (same channels in lane cl and 16+cl)
    ps.x += __shfl_down_sync(0xffffffffu, ps.x, 16);
    ps.y += __shfl_down_sync(0xffffffffu, ps.y, 16);
    ps.z += __shfl_down_sync(0xffffffffu, ps.z, 16);
    ps.w += __shfl_down_sync(0xffffffffu, ps.w, 16);
    pq.x += __shfl_down_sync(0xffffffffu, pq.x, 16);
    pq.y += __shfl_down_sync(0xffffffffu, pq.y, 16);
    pq.z += __shfl_down_sync(0xffffffffu, pq.z, 16);
    pq.w += __shfl_down_sync(0xffffffffu, pq.w, 16);
    if (eh == 0) {
        float* sb = &sred[warp * 128];
        int c4 = cl * 4;
        sb[c4 + 0] = ps.x; sb[c4 + 1] = ps.y; sb[c4 + 2] = ps.z; sb[c4 + 3] = ps.w;
        sb[64 + c4 + 0] = pq.x; sb[64 + c4 + 1] = pq.y; sb[64 + c4 + 2] = pq.z; sb[64 + c4 + 3] = pq.w;
    }
    __syncthreads();
    if (tid < 128) {
        float v = 0.f;
#pragma unroll
        for (int w = 0; w < 8; w++) v += sred[w * 128 + tid];
        g_part2[blockIdx.x * 128 + tid] = v;
    }
}

__global__ void __launch_bounds__(256) k_red2(
    const float* __restrict__ g2, const float* __restrict__ b2)
{
    __shared__ float ssum[256], ssq[256];
    int c = blockIdx.x;
    int t = threadIdx.x;
    float s = 0.f, q = 0.f;
    for (int r = t; r < DGRID; r += 256) {
        s += g_part2[r * 128 + c];
        q += g_part2[r * 128 + 64 + c];
    }
    ssum[t] = s; ssq[t] = q;
    __syncthreads();
    for (int o = 128; o; o >>= 1) {
        if (t < o) { ssum[t] += ssum[t + o]; ssq[t] += ssq[t + o]; }
        __syncthreads();
    }
    if (t == 0) {
        const float invN = 1.f / (float)N_NODES;
        float mu = ssum[0] * invN;
        float var = ssq[0] * invN - mu * mu;
        float sc = rsqrtf(var + EPS_BN) * g2[c];
        g_bn2sc[c] = sc;
        g_bn2sh[c] = fmaf(-mu, sc, b2[c]);
    }
}

// ---------------- launch ----------------
extern "C" void kernel_launch(void* const* d_in, const int* in_sizes, int n_in,
                              void* d_out, int out_size)
{
    const float* x     = (const float*)d_in[0];
    const int*   ei    = (const int*)  d_in[1];
    const float* ea    = (const float*)d_in[2];
    const int*   bs    = (const int*)  d_in[3];
    const float* att   = (const float*)d_in[4];
    const float* embW  = (const float*)d_in[5];
    const float* embb  = (const float*)d_in[6];
    const float* adw1  = (const float*)d_in[7];
    const float* adb1  = (const float*)d_in[8];
    const float* adw2  = (const float*)d_in[9];
    const float* adb2  = (const float*)d_in[10];
    const float* adal  = (const float*)d_in[11];
    const float* adlut = (const float*)d_in[12];
    const float* fcW   = (const float*)d_in[13];
    const float* fcb   = (const float*)d_in[14];
    const float* bn1g  = (const float*)d_in[15];
    const float* bn1b  = (const float*)d_in[16];
    const float* bn2g  = (const float*)d_in[17];
    const float* bn2b  = (const float*)d_in[18];
    const float* ppW   = (const float*)d_in[19];
    const float* ppb   = (const float*)d_in[20];
    float* out = (float*)d_out;

    k_hist<<<N_EDGES / 1024, 1024>>>(ei, out, out_size);
    k_scan<<<1, 1024>>>();
    k_scatter<<<N_EDGES / 1024, 1024>>>(ei, ea);
    k_embed_pool<<<N_NODES / PB, 256>>>(x, att, embW, embb, ppW, ppb, out, bs);

    for (int l = 0; l < NCONV; l++) {
        k_table<<<TBL, FCO>>>(adw1 + l * BINS, adb1 + l * BINS,
                              adw2 + l * BINS * BINS, adb2 + l * BINS,
                              adal + l, adlut + l * BINS * AFL,
                              fcW + l * (3 * AFL) * FCO, fcb + l * FCO);
        k_proj<<<N_NODES / PROJ_ROWS, 256>>>(fcW + l * (3 * AFL) * FCO);
        k_edgeC<<<EGRID, 256>>>();
        k_red1<<<FCO, 256>>>(bn1g + l * FCO, bn1b + l * FCO);
        k_edgeD<<<DGRID, 256>>>();
        k_red2<<<AFL, 256>>>(bn2g + l * AFL, bn2b + l * AFL);
        k_update_pool<<<N_NODES / PB, 256>>>(ppW, ppb, out, bs);
    }
}

// round 13
// speedup vs baseline: 1.0114x; 1.0114x over previous
#include <cuda_runtime.h>
#include <cuda_bf16.h>
#include <cstdint>

#define N_NODES 51200
#define N_EDGES 614400
#define ORIG    92
#define AFL     64
#define BINS    100
#define NCONV   3
#define TBL     128
#define FCO     128      // 2*AFL
#define EPS_BN  1e-5f
#define EGRID   1024
#define DGRID   1024
#define PROJ_ROWS 64
#define HPAD    68
#define PB      64
#define HT_PAD  68
#define KC      32

typedef unsigned long long u64;
__device__ __forceinline__ u64 pack2(float lo, float hi) {
    u64 r; asm("mov.b64 %0, {%1, %2};" : "=l"(r) : "f"(lo), "f"(hi)); return r;
}
__device__ __forceinline__ void unpack2(u64 v, float& lo, float& hi) {
    asm("mov.b64 {%0, %1}, %2;" : "=f"(lo), "=f"(hi) : "l"(v));
}
__device__ __forceinline__ u64 fma2(u64 a, u64 b, u64 c) {
    u64 d; asm("fma.rn.f32x2 %0, %1, %2, %3;" : "=l"(d) : "l"(a), "l"(b), "l"(c));
    return d;
}

// ---------------- device scratch (static, no allocations) ----------------
__device__ float g_h[N_NODES * AFL];
__device__ float g_Zd[N_NODES * FCO];
__device__ float g_Zs[N_NODES * FCO];
__device__ float g_T[TBL * FCO];
__device__ float g_aggr[N_NODES * AFL];
__device__ float g_part1[EGRID * 256];
__device__ float g_part2[DGRID * 128];
__device__ float g_bn1sc[FCO], g_bn1sh[FCO];
__device__ float g_bn2sc[AFL], g_bn2sh[AFL];
__device__ int   g_cnt[N_NODES];              // zero-init; re-zeroed by k_scan
__device__ int   g_segstart[N_NODES + 1];
__device__ int   g_off[N_NODES];
__device__ int   g_psrc[N_EDGES];
__device__ int   g_pdst[N_EDGES];
__device__ float g_pattr[N_EDGES];

// ---------------- edge sort ----------------
__global__ void __launch_bounds__(1024) k_hist(const int* __restrict__ ei,
                                               float* __restrict__ out, int osz) {
    int e = blockIdx.x * blockDim.x + threadIdx.x;
    if (e < osz) out[e] = 0.f;
    if (e < N_EDGES) atomicAdd(&g_cnt[ei[N_EDGES + e]], 1);
}

__global__ void __launch_bounds__(1024) k_scan() {
    __shared__ int wsum[32];
    __shared__ int carry;
    int tid = threadIdx.x;
    int lane = tid & 31, wid = tid >> 5;
    if (tid == 0) carry = 0;
    __syncthreads();
    for (int base = 0; base < N_NODES; base += 1024) {
        int v = g_cnt[base + tid];
        g_cnt[base + tid] = 0;
        int x = v;
#pragma unroll
        for (int o = 1; o < 32; o <<= 1) {
            int t = __shfl_up_sync(0xffffffffu, x, o);
            if (lane >= o) x += t;
        }
        if (lane == 31) wsum[wid] = x;
        __syncthreads();
        if (wid == 0) {
            int sv = wsum[lane];
#pragma unroll
            for (int o = 1; o < 32; o <<= 1) {
                int t = __shfl_up_sync(0xffffffffu, sv, o);
                if (lane >= o) sv += t;
            }
            wsum[lane] = sv;
        }
        __syncthreads();
        int woff = (wid > 0) ? wsum[wid - 1] : 0;
        int ex = carry + woff + x - v;
        g_segstart[base + tid] = ex;
        g_off[base + tid] = ex;
        __syncthreads();
        if (tid == 0) carry += wsum[31];
        __syncthreads();
    }
    if (tid == 0) g_segstart[N_NODES] = N_EDGES;
}

__global__ void __launch_bounds__(1024) k_scatter(const int* __restrict__ ei,
                                                  const float* __restrict__ ea) {
    int e = blockIdx.x * blockDim.x + threadIdx.x;
    if (e < N_EDGES) {
        int dst = ei[N_EDGES + e];
        int pos = atomicAdd(&g_off[dst], 1);
        g_psrc[pos] = ei[e];
        g_pdst[pos] = dst;
        g_pattr[pos] = ea[e];
    }
}

// ---------------- shared pool helper (f32x2 GEMM + softmax + output) ----------------
__device__ __forceinline__ void pool_tile(
    const float* __restrict__ ppWs, const float* __restrict__ hsT,
    float* __restrict__ red, const float* __restrict__ ppb,
    float* __restrict__ out, int n0, int numAtom, int tx, int ty, int tid)
{
    const u64*    W2 = reinterpret_cast<const u64*>(ppWs);
    const float4* H4 = reinterpret_cast<const float4*>(hsT);
    float4 pb = *reinterpret_cast<const float4*>(ppb + 4 * tx);
    // a[r][cp]: row r (node 4*ty+r), column pair cp (cols 4tx+2cp, +1)
    u64 a[4][2];
#pragma unroll
    for (int r = 0; r < 4; r++) {
        a[r][0] = pack2(pb.x, pb.y);
        a[r][1] = pack2(pb.z, pb.w);
    }
#pragma unroll 8
    for (int k = 0; k < AFL; k++) {
        u64 w01 = W2[k * 32 + 2 * tx];
        u64 w23 = W2[k * 32 + 2 * tx + 1];
        float4 h4 = H4[k * (HT_PAD / 4) + ty];
        u64 hd0 = pack2(h4.x, h4.x);
        u64 hd1 = pack2(h4.y, h4.y);
        u64 hd2 = pack2(h4.z, h4.z);
        u64 hd3 = pack2(h4.w, h4.w);
        a[0][0] = fma2(hd0, w01, a[0][0]); a[0][1] = fma2(hd0, w23, a[0][1]);
        a[1][0] = fma2(hd1, w01, a[1][0]); a[1][1] = fma2(hd1, w23, a[1][1]);
        a[2][0] = fma2(hd2, w01, a[2][0]); a[2][1] = fma2(hd2, w23, a[2][1]);
        a[3][0] = fma2(hd3, w01, a[3][0]); a[3][1] = fma2(hd3, w23, a[3][1]);
    }
    float4 val[4];
#pragma unroll
    for (int i = 0; i < 4; i++) {
        float4 p;
        unpack2(a[i][0], p.x, p.y);
        unpack2(a[i][1], p.z, p.w);
        float m = fmaxf(fmaxf(p.x, p.y), fmaxf(p.z, p.w));
#pragma unroll
        for (int o = 1; o < 16; o <<= 1)
            m = fmaxf(m, __shfl_xor_sync(0xffffffffu, m, o));
        float4 e;
        e.x = expf(p.x - m); e.y = expf(p.y - m);
        e.z = expf(p.z - m); e.w = expf(p.w - m);
        float s = (e.x + e.y) + (e.z + e.w);
#pragma unroll
        for (int o = 1; o < 16; o <<= 1)
            s += __shfl_xor_sync(0xffffffffu, s, o);
        float inv = 1.f / s;
        val[i] = make_float4(e.x * inv, e.y * inv, e.z * inv, e.w * inv);
    }
    bool same = (n0 / numAtom) == ((n0 + PB - 1) / numAtom);
    if (same) {
        float4 cs;
        cs.x = (val[0].x + val[1].x) + (val[2].x + val[3].x);
        cs.y = (val[0].y + val[1].y) + (val[2].y + val[3].y);
        cs.z = (val[0].z + val[1].z) + (val[2].z + val[3].z);
        cs.w = (val[0].w + val[1].w) + (val[2].w + val[3].w);
        *reinterpret_cast<float4*>(&red[ty * 64 + 4 * tx]) = cs;
        __syncthreads();
        if (tid < 64) {
            float s = 0.f;
#pragma unroll
            for (int r = 0; r < 16; r++) s += red[r * 64 + tid];
            atomicAdd(&out[(n0 / numAtom) * AFL + tid], s);
        }
    } else {
#pragma unroll
        for (int i = 0; i < 4; i++) {
            int node = n0 + 4 * ty + i;
            int cry = node / numAtom;
            atomicAdd(&out[cry * AFL + 4 * tx + 0], val[i].x);
            atomicAdd(&out[cry * AFL + 4 * tx + 1], val[i].y);
            atomicAdd(&out[cry * AFL + 4 * tx + 2], val[i].z);
            atomicAdd(&out[cry * AFL + 4 * tx + 3], val[i].w);
        }
    }
}

// ---------------- embedding + initial pooling ----------------
__global__ void __launch_bounds__(256) k_embed_pool(
    const float* __restrict__ x, const float* __restrict__ att,
    const float* __restrict__ W, const float* __restrict__ b,
    const float* __restrict__ ppW, const float* __restrict__ ppb,
    float* __restrict__ out, const int* __restrict__ bs)
{
    __shared__ float sbuf[KC * AFL + KC * HT_PAD];
    __shared__ float hsT[AFL * HT_PAD];
    __shared__ float red[16 * AFL];
    float* Wc = sbuf;
    float* xsT = sbuf + KC * AFL;
    int tid = threadIdx.x;
    int tx = tid & 15, ty = tid >> 4;
    int n0 = blockIdx.x * PB;

    float4 b4 = *reinterpret_cast<const float4*>(b + 4 * tx);
    u64 a[4][2];
#pragma unroll
    for (int r = 0; r < 4; r++) {
        a[r][0] = pack2(b4.x, b4.y);
        a[r][1] = pack2(b4.z, b4.w);
    }

    for (int kc = 0; kc < ORIG; kc += KC) {
        int kl = min(KC, ORIG - kc);
        __syncthreads();
        for (int i = tid; i < kl * AFL; i += 256) Wc[i] = W[kc * AFL + i];
        for (int idx = tid; idx < PB * KC; idx += 256) {
            int n = idx >> 5, k = idx & 31;
            if (k < kl)
                xsT[k * HT_PAD + n] = x[(size_t)(n0 + n) * ORIG + kc + k] * att[kc + k];
        }
        __syncthreads();
        const u64*    Wc2 = reinterpret_cast<const u64*>(Wc);
        const float4* X4 = reinterpret_cast<const float4*>(xsT);
#pragma unroll 4
        for (int k = 0; k < kl; k++) {
            u64 w01 = Wc2[k * 32 + 2 * tx];
            u64 w23 = Wc2[k * 32 + 2 * tx + 1];
            float4 h4 = X4[k * (HT_PAD / 4) + ty];
            u64 hd0 = pack2(h4.x, h4.x);
            u64 hd1 = pack2(h4.y, h4.y);
            u64 hd2 = pack2(h4.z, h4.z);
            u64 hd3 = pack2(h4.w, h4.w);
            a[0][0] = fma2(hd0, w01, a[0][0]); a[0][1] = fma2(hd0, w23, a[0][1]);
            a[1][0] = fma2(hd1, w01, a[1][0]); a[1][1] = fma2(hd1, w23, a[1][1]);
            a[2][0] = fma2(hd2, w01, a[2][0]); a[2][1] = fma2(hd2, w23, a[2][1]);
            a[3][0] = fma2(hd3, w01, a[3][0]); a[3][1] = fma2(hd3, w23, a[3][1]);
        }
    }
#pragma unroll
    for (int i = 0; i < 4; i++) {
        float4 av;
        unpack2(a[i][0], av.x, av.y);
        unpack2(a[i][1], av.z, av.w);
        int node = n0 + 4 * ty + i;
        *reinterpret_cast<float4*>(&g_h[(size_t)node * AFL + 4 * tx]) = av;
        hsT[(4 * tx + 0) * HT_PAD + 4 * ty + i] = av.x;
        hsT[(4 * tx + 1) * HT_PAD + 4 * ty + i] = av.y;
        hsT[(4 * tx + 2) * HT_PAD + 4 * ty + i] = av.z;
        hsT[(4 * tx + 3) * HT_PAD + 4 * ty + i] = av.w;
    }
    __syncthreads();
    for (int i = tid; i < AFL * AFL; i += 256) sbuf[i] = ppW[i];
    __syncthreads();
    int numAtom = N_NODES / bs[0];
    pool_tile(sbuf, hsT, red, ppb, out, n0, numAtom, tx, ty, tid);
}

// ---------------- update + pooling ----------------
__global__ void __launch_bounds__(256) k_update_pool(
    const float* __restrict__ ppW, const float* __restrict__ ppb,
    float* __restrict__ out, const int* __restrict__ bs)
{
    __shared__ float ppWs[AFL * AFL];
    __shared__ float hsT[AFL * HT_PAD];
    __shared__ float red[16 * AFL];
    int tid = threadIdx.x;
    int tx = tid & 15, ty = tid >> 4;
    int n0 = blockIdx.x * PB;

    for (int i = tid; i < AFL * AFL; i += 256) ppWs[i] = ppW[i];
    for (int idx = tid; idx < PB * 16; idx += 256) {
        int n = idx >> 4, c4 = idx & 15;
        size_t base = (size_t)(n0 + n) * AFL + 4 * c4;
        float4 h4 = *reinterpret_cast<const float4*>(&g_h[base]);
        float4 g4 = *reinterpret_cast<const float4*>(&g_aggr[base]);
        float4 sc = reinterpret_cast<const float4*>(g_bn2sc)[c4];
        float4 sh = reinterpret_cast<const float4*>(g_bn2sh)[c4];
        float4 up;
        up.x = fmaxf(h4.x + fmaf(g4.x, sc.x, sh.x), 0.f);
        up.y = fmaxf(h4.y + fmaf(g4.y, sc.y, sh.y), 0.f);
        up.z = fmaxf(h4.z + fmaf(g4.z, sc.z, sh.z), 0.f);
        up.w = fmaxf(h4.w + fmaf(g4.w, sc.w, sh.w), 0.f);
        *reinterpret_cast<float4*>(&g_h[base]) = up;
        hsT[(4 * c4 + 0) * HT_PAD + n] = up.x;
        hsT[(4 * c4 + 1) * HT_PAD + n] = up.y;
        hsT[(4 * c4 + 2) * HT_PAD + n] = up.z;
        hsT[(4 * c4 + 3) * HT_PAD + n] = up.w;
    }
    __syncthreads();
    int numAtom = N_NODES / bs[0];
    pool_tile(ppWs, hsT, red, ppb, out, n0, numAtom, tx, ty, tid);
}

// ---------------- fused table ----------------
__global__ void __launch_bounds__(FCO) k_table(
    const float* __restrict__ w1, const float* __restrict__ b1,
    const float* __restrict__ w2, const float* __restrict__ b2,
    const float* __restrict__ alpha, const float* __restrict__ lut,
    const float* __restrict__ fcW, const float* __restrict__ fcb)
{
    __shared__ float v2[BINS];
    __shared__ float p[BINS];
    __shared__ float q[AFL];
    __shared__ float redA[4];
    __shared__ float redB[4];
    int tid = threadIdx.x;
    float a = (float)blockIdx.x / (float)(TBL - 1);
    if (tid < BINS) {
        float v = fmaf(a, w1[tid], b1[tid]);
        v2[tid] = v > 0.f ? v : 0.01f * v;
    }
    __syncthreads();
    float v3 = -3.0e38f;
    if (tid < BINS) {
        float acc = fmaf(alpha[0], v2[tid], b2[tid]);
#pragma unroll 4
        for (int k = 0; k < BINS; k++) acc = fmaf(v2[k], w2[k * BINS + tid], acc);
        v3 = acc;
    }
    float m = v3;
#pragma unroll
    for (int o = 16; o; o >>= 1) m = fmaxf(m, __shfl_xor_sync(0xffffffffu, m, o));
    if ((tid & 31) == 0) redA[tid >> 5] = m;
    __syncthreads();
    m = fmaxf(fmaxf(redA[0], redA[1]), fmaxf(redA[2], redA[3]));
    float ex = (tid < BINS) ? expf(v3 - m) : 0.f;
    float s = ex;
#pragma unroll
    for (int o = 16; o; o >>= 1) s += __shfl_xor_sync(0xffffffffu, s, o);
    if ((tid & 31) == 0) redB[tid >> 5] = s;
    __syncthreads();
    s = (redB[0] + redB[1]) + (redB[2] + redB[3]);
    float inv = 1.f / s;
    if (tid < BINS) p[tid] = ex * inv;
    __syncthreads();
    if (tid < AFL) {
        float acc = 0.f;
#pragma unroll 4
        for (int j = 0; j < BINS; j++) acc = fmaf(p[j], lut[j * AFL + tid], acc);
        q[tid] = acc;
    }
    __syncthreads();
    float acc = fcb[tid];
#pragma unroll 4
    for (int mm = 0; mm < AFL; mm++)
        acc = fmaf(q[mm], fcW[(2 * AFL + mm) * FCO + tid], acc);
    g_T[blockIdx.x * FCO + tid] = acc;
}

// ---------------- node projections: f32x2-packed register tile (R11 best) ----------------
__global__ void __launch_bounds__(256) k_proj(const float* __restrict__ fcW)
{
    __shared__ float Wsh[16 * 256];
    __shared__ float hsh[AFL * HPAD];
    int tid = threadIdx.x;
    int tx = tid & 63;
    int ty = tid >> 6;
    int r0 = blockIdx.x * PROJ_ROWS;
    int col = 4 * tx;

    for (int i = tid; i < PROJ_ROWS * AFL; i += 256) {
        int r = i >> 6, k = i & 63;
        hsh[k * HPAD + r] = g_h[(size_t)(r0 + r) * AFL + k];
    }

    u64 accP[8][4];
    u64 zero = pack2(0.f, 0.f);
#pragma unroll
    for (int p = 0; p < 8; p++)
#pragma unroll
        for (int c = 0; c < 4; c++) accP[p][c] = zero;

    for (int kc = 0; kc < 4; kc++) {
        __syncthreads();
        for (int i = tid; i < 16 * 256; i += 256) {
            int kk = i >> 8;
            int cl = i & 255;
            int h2 = cl >> 7, c2 = cl & 127;
            Wsh[i] = fcW[(size_t)(h2 * AFL + kc * 16 + kk) * FCO + c2];
        }
        __syncthreads();
#pragma unroll
        for (int kk = 0; kk < 16; kk++) {
            float4 w4 = *reinterpret_cast<const float4*>(&Wsh[kk * 256 + col]);
            u64 wd0 = pack2(w4.x, w4.x);
            u64 wd1 = pack2(w4.y, w4.y);
            u64 wd2 = pack2(w4.z, w4.z);
            u64 wd3 = pack2(w4.w, w4.w);
            const u64* hp = reinterpret_cast<const u64*>(
                &hsh[(kc * 16 + kk) * HPAD + ty * 16]);
#pragma unroll
            for (int p = 0; p < 8; p++) {
                u64 h2v = hp[p];
                accP[p][0] = fma2(h2v, wd0, accP[p][0]);
                accP[p][1] = fma2(h2v, wd1, accP[p][1]);
                accP[p][2] = fma2(h2v, wd2, accP[p][2]);
                accP[p][3] = fma2(h2v, wd3, accP[p][3]);
            }
        }
    }
    int half = col >> 7;
    int cc = col & 127;
    float* dst = half ? g_Zs : g_Zd;
#pragma unroll
    for (int p = 0; p < 8; p++) {
        float4 lo4, hi4;
        unpack2(accP[p][0], lo4.x, hi4.x);
        unpack2(accP[p][1], lo4.y, hi4.y);
        unpack2(accP[p][2], lo4.z, hi4.z);
        unpack2(accP[p][3], lo4.w, hi4.w);
        *reinterpret_cast<float4*>(&dst[(size_t)(r0 + ty * 16 + 2 * p) * FCO + cc]) = lo4;
        *reinterpret_cast<float4*>(&dst[(size_t)(r0 + ty * 16 + 2 * p + 1) * FCO + cc]) = hi4;
    }
}

// ---------------- pass C: flat edge-parallel BN1 stats (R8 best) ----------------
__global__ void __launch_bounds__(256) k_edgeC()
{
    __shared__ float sred[8 * 256];
    int tid = threadIdx.x;
    int warp = tid >> 5, lane = tid & 31;
    int gwarp = blockIdx.x * 8 + warp;
    int nwarp = gridDim.x * 8;
    const float4* T4  = reinterpret_cast<const float4*>(g_T);
    const float4* Zd4 = reinterpret_cast<const float4*>(g_Zd);
    const float4* Zs4 = reinterpret_cast<const float4*>(g_Zs);
    float4 ps = {0,0,0,0}, pq = {0,0,0,0};

    for (int e0 = gwarp * 4; e0 < N_EDGES; e0 += nwarp * 4) {
        int4   ss = __ldg(reinterpret_cast<const int4*>(g_psrc + e0));
        int4   dd = __ldg(reinterpret_cast<const int4*>(g_pdst + e0));
        float4 aa = __ldg(reinterpret_cast<const float4*>(g_pattr + e0));
        float4 zs0 = __ldg(Zs4 + (size_t)ss.x * 32 + lane);
        float4 zs1 = __ldg(Zs4 + (size_t)ss.y * 32 + lane);
        float4 zs2 = __ldg(Zs4 + (size_t)ss.z * 32 + lane);
        float4 zs3 = __ldg(Zs4 + (size_t)ss.w * 32 + lane);
        float4 zd0 = __ldg(Zd4 + (size_t)dd.x * 32 + lane);
        float4 zd1 = __ldg(Zd4 + (size_t)dd.y * 32 + lane);
        float4 zd2 = __ldg(Zd4 + (size_t)dd.z * 32 + lane);
        float4 zd3 = __ldg(Zd4 + (size_t)dd.w * 32 + lane);

#define DOEDGE_C(ZD, ZS, A)                                                  \
        {                                                                    \
            float pos = fminf(fmaxf((A) * (float)(TBL - 1), 0.f),            \
                              (float)(TBL - 1));                             \
            int t0 = min((int)pos, TBL - 2);                                 \
            float w = pos - (float)t0;                                       \
            float4 T0 = __ldg(T4 + t0 * 32 + lane);                          \
            float4 T1 = __ldg(T4 + (t0 + 1) * 32 + lane);                    \
            float zx = ZD.x + ZS.x + fmaf(w, T1.x - T0.x, T0.x);             \
            float zy = ZD.y + ZS.y + fmaf(w, T1.y - T0.y, T0.y);             \
            float zz = ZD.z + ZS.z + fmaf(w, T1.z - T0.z, T0.z);             \
            float zw = ZD.w + ZS.w + fmaf(w, T1.w - T0.w, T0.w);             \
            ps.x += zx; ps.y += zy; ps.z += zz; ps.w += zw;                  \
            pq.x = fmaf(zx, zx, pq.x); pq.y = fmaf(zy, zy, pq.y);            \
            pq.z = fmaf(zz, zz, pq.z); pq.w = fmaf(zw, zw, pq.w);            \
        }
        DOEDGE_C(zd0, zs0, aa.x)
        DOEDGE_C(zd1, zs1, aa.y)
        DOEDGE_C(zd2, zs2, aa.z)
        DOEDGE_C(zd3, zs3, aa.w)
#undef DOEDGE_C
    }
    {
        float* sb = &sred[warp * 256];
        int c4 = lane * 4;
        sb[c4 + 0] = ps.x; sb[c4 + 1] = ps.y; sb[c4 + 2] = ps.z; sb[c4 + 3] = ps.w;
        sb[128 + c4 + 0] = pq.x; sb[128 + c4 + 1] = pq.y;
        sb[128 + c4 + 2] = pq.z; sb[128 + c4 + 3] = pq.w;
    }
    __syncthreads();
    float v = 0.f;
#pragma unroll
    for (int w = 0; w < 8; w++) v += sred[w * 256 + tid];
    g_part1[blockIdx.x * 256 + tid] = v;
}

__global__ void __launch_bounds__(256) k_red1(
    const float* __restrict__ g1, const float* __restrict__ b1)
{
    __shared__ float ssum[256], ssq[256];
    int c = blockIdx.x;
    int t = threadIdx.x;
    float s = 0.f, q = 0.f;
    for (int r = t; r < EGRID; r += 256) {
        s += g_part1[r * 256 + c];
        q += g_part1[r * 256 + 128 + c];
    }
    ssum[t] = s; ssq[t] = q;
    __syncthreads();
    for (int o = 128; o; o >>= 1) {
        if (t < o) { ssum[t] += ssum[t + o]; ssq[t] += ssq[t + o]; }
        __syncthreads();
    }
    if (t == 0) {
        const float invE = 1.f / (float)N_EDGES;
        float mu = ssum[0] * invE;
        float var = ssq[0] * invE - mu * mu;
        float sc = rsqrtf(var + EPS_BN) * g1[c];
        g_bn1sc[c] = sc;
        g_bn1sh[c] = fmaf(-mu, sc, b1[c]);
    }
}

// ---------------- pass D: segment 4-wide (R9/R11 best — final form) ----------------
__global__ void __launch_bounds__(256) k_edgeD()
{
    __shared__ float sred[8 * 128];
    int tid = threadIdx.x;
    int warp = tid >> 5, lane = tid & 31;
    int cl = lane & 15, eh = lane >> 4;
    int gw = blockIdx.x * 8 + warp;
    int nw = gridDim.x * 8;
    const float4* T4 = reinterpret_cast<const float4*>(g_T);
    float4 sc0 = reinterpret_cast<const float4*>(g_bn1sc)[cl];
    float4 sc1 = reinterpret_cast<const float4*>(g_bn1sc)[16 + cl];
    float4 sh0 = reinterpret_cast<const float4*>(g_bn1sh)[cl];
    float4 sh1 = reinterpret_cast<const float4*>(g_bn1sh)[16 + cl];
    float4 ps = {0,0,0,0}, pq = {0,0,0,0};

    for (int n = gw; n < N_NODES; n += nw) {
        int beg = g_segstart[n], end = g_segstart[n + 1];
        float4 acc = {0,0,0,0};
        if (beg < end) {
            const float4* zdp = reinterpret_cast<const float4*>(&g_Zd[(size_t)n * FCO]);
            float4 zd0 = __ldg(zdp + cl), zd1 = __ldg(zdp + 16 + cl);

            auto doedge = [&](const float4& zs0, const float4& zs1, float a) {
                float pos = fminf(fmaxf(a * (float)(TBL - 1), 0.f), (float)(TBL - 1));
                int t0 = min((int)pos, TBL - 2);
                float w = pos - (float)t0;
                float4 T0l = __ldg(T4 + t0 * 32 + cl);
                float4 T0h = __ldg(T4 + t0 * 32 + 16 + cl);
                float4 T1l = __ldg(T4 + (t0 + 1) * 32 + cl);
                float4 T1h = __ldg(T4 + (t0 + 1) * 32 + 16 + cl);
                float4 z0, z1;
                z0.x = zd0.x + zs0.x + fmaf(w, T1l.x - T0l.x, T0l.x);
                z0.y = zd0.y + zs0.y + fmaf(w, T1l.y - T0l.y, T0l.y);
                z0.z = zd0.z + zs0.z + fmaf(w, T1l.z - T0l.z, T0l.z);
                z0.w = zd0.w + zs0.w + fmaf(w, T1l.w - T0l.w, T0l.w);
                z1.x = zd1.x + zs1.x + fmaf(w, T1h.x - T0h.x, T0h.x);
                z1.y = zd1.y + zs1.y + fmaf(w, T1h.y - T0h.y, T0h.y);
                z1.z = zd1.z + zs1.z + fmaf(w, T1h.z - T0h.z, T0h.z);
                z1.w = zd1.w + zs1.w + fmaf(w, T1h.w - T0h.w, T0h.w);
                float fx = fmaxf(fmaf(z0.x, sc0.x, sh0.x), 0.f);
                float fy = fmaxf(fmaf(z0.y, sc0.y, sh0.y), 0.f);
                float fz = fmaxf(fmaf(z0.z, sc0.z, sh0.z), 0.f);
                float fw = fmaxf(fmaf(z0.w, sc0.w, sh0.w), 0.f);
                float gx = fmaxf(fmaf(z1.x, sc1.x, sh1.x), 0.f);
                float gy = fmaxf(fmaf(z1.y, sc1.y, sh1.y), 0.f);
                float gz = fmaxf(fmaf(z1.z, sc1.z, sh1.z), 0.f);
                float gw2 = fmaxf(fmaf(z1.w, sc1.w, sh1.w), 0.f);
                acc.x = fmaf(fx, gx, acc.x);
                acc.y = fmaf(fy, gy, acc.y);
                acc.z = fmaf(fz, gz, acc.z);
                acc.w = fmaf(fw, gw2, acc.w);
            };

            for (int base = beg; base < end; base += 32) {
                int e = base + lane;
                int sv = 0; float av = 0.f;
                if (e < end) { sv = g_psrc[e]; av = g_pattr[e]; }
                int cnt = min(32, end - base);
                int j = 0;
                for (; j + 4 <= cnt; j += 4) {
                    int iA = j + eh, iB = j + 2 + eh;
                    int sA = __shfl_sync(0xffffffffu, sv, iA);
                    int sB = __shfl_sync(0xffffffffu, sv, iB);
                    float aA = __shfl_sync(0xffffffffu, av, iA);
                    float aB = __shfl_sync(0xffffffffu, av, iB);
                    const float4* zA = reinterpret_cast<const float4*>(&g_Zs[(size_t)sA * FCO]);
                    const float4* zB = reinterpret_cast<const float4*>(&g_Zs[(size_t)sB * FCO]);
                    float4 zA0 = __ldg(zA + cl), zA1 = __ldg(zA + 16 + cl);
                    float4 zB0 = __ldg(zB + cl), zB1 = __ldg(zB + 16 + cl);
                    doedge(zA0, zA1, aA);
                    doedge(zB0, zB1, aB);
                }
                for (; j + 2 <= cnt; j += 2) {
                    int iA = j + eh;
                    int sA = __shfl_sync(0xffffffffu, sv, iA);
                    float aA = __shfl_sync(0xffffffffu, av, iA);
                    const float4* zA = reinterpret_cast<const float4*>(&g_Zs[(size_t)sA * FCO]);
                    float4 zA0 = __ldg(zA + cl), zA1 = __ldg(zA + 16 + cl);
                    doedge(zA0, zA1, aA);
                }
                if (j < cnt) {
                    int sA = __shfl_sync(0xffffffffu, sv, j);
                    float aA = __shfl_sync(0xffffffffu, av, j);
                    if (eh == 0) {
                        const float4* zA = reinterpret_cast<const float4*>(&g_Zs[(size_t)sA * FCO]);
                        float4 zA0 = __ldg(zA + cl), zA1 = __ldg(zA + 16 + cl);
                        doedge(zA0, zA1, aA);
                    }
                }
            }
        }
        acc.x += __shfl_down_sync(0xffffffffu, acc.x, 16);
        acc.y += __shfl_down_sync(0xffffffffu, acc.y, 16);
        acc.z += __shfl_down_sync(0xffffffffu, acc.z, 16);
        acc.w += __shfl_down_sync(0xffffffffu, acc.w, 16);
        if (eh == 0) {
            reinterpret_cast<float4*>(&g_aggr[(size_t)n * AFL])[cl] = acc;
            ps.x += acc.x; ps.y += acc.y; ps.z += acc.z; ps.w += acc.w;
            pq.x = fmaf(acc.x, acc.x, pq.x); pq.y = fmaf(acc.y, acc.y, pq.y);
            pq.z = fmaf(acc.z, acc.z, pq.z); pq.w = fmaf(acc.w, acc.w, pq.w);
        }
    }
    if (eh == 0) {
        float* sb = &sred[warp * 128];
        int c4 = cl * 4;
        sb[c4 + 0] = ps.x; sb[c4 + 1] = ps.y; sb[c4 + 2] = ps.z; sb[c4 + 3] = ps.w;
        sb[64 + c4 + 0] = pq.x; sb[64 + c4 + 1] = pq.y; sb[64 + c4 + 2] = pq.z; sb[64 + c4 + 3] = pq.w;
    }
    __syncthreads();
    if (tid < 128) {
        float v = 0.f;
#pragma unroll
        for (int w = 0; w < 8; w++) v += sred[w * 128 + tid];
        g_part2[blockIdx.x * 128 + tid] = v;
    }
}

__global__ void __launch_bounds__(256) k_red2(
    const float* __restrict__ g2, const float* __restrict__ b2)
{
    __shared__ float ssum[256], ssq[256];
    int c = blockIdx.x;
    int t = threadIdx.x;
    float s = 0.f, q = 0.f;
    for (int r = t; r < DGRID; r += 256) {
        s += g_part2[r * 128 + c];
        q += g_part2[r * 128 + 64 + c];
    }
    ssum[t] = s; ssq[t] = q;
    __syncthreads();
    for (int o = 128; o; o >>= 1) {
        if (t < o) { ssum[t] += ssum[t + o]; ssq[t] += ssq[t + o]; }
        __syncthreads();
    }
    if (t == 0) {
        const float invN = 1.f / (float)N_NODES;
        float mu = ssum[0] * invN;
        float var = ssq[0] * invN - mu * mu;
        float sc = rsqrtf(var + EPS_BN) * g2[c];
        g_bn2sc[c] = sc;
        g_bn2sh[c] = fmaf(-mu, sc, b2[c]);
    }
}

// ---------------- launch ----------------
extern "C" void kernel_launch(void* const* d_in, const int* in_sizes, int n_in,
                              void* d_out, int out_size)
{
    const float* x     = (const float*)d_in[0];
    const int*   ei    = (const int*)  d_in[1];
    const float* ea    = (const float*)d_in[2];
    const int*   bs    = (const int*)  d_in[3];
    const float* att   = (const float*)d_in[4];
    const float* embW  = (const float*)d_in[5];
    const float* embb  = (const float*)d_in[6];
    const float* adw1  = (const float*)d_in[7];
    const float* adb1  = (const float*)d_in[8];
    const float* adw2  = (const float*)d_in[9];
    const float* adb2  = (const float*)d_in[10];
    const float* adal  = (const float*)d_in[11];
    const float* adlut = (const float*)d_in[12];
    const float* fcW   = (const float*)d_in[13];
    const float* fcb   = (const float*)d_in[14];
    const float* bn1g  = (const float*)d_in[15];
    const float* bn1b  = (const float*)d_in[16];
    const float* bn2g  = (const float*)d_in[17];
    const float* bn2b  = (const float*)d_in[18];
    const float* ppW   = (const float*)d_in[19];
    const float* ppb   = (const float*)d_in[20];
    float* out = (float*)d_out;

    k_hist<<<N_EDGES / 1024, 1024>>>(ei, out, out_size);
    k_scan<<<1, 1024>>>();
    k_scatter<<<N_EDGES / 1024, 1024>>>(ei, ea);
    k_embed_pool<<<N_NODES / PB, 256>>>(x, att, embW, embb, ppW, ppb, out, bs);

    for (int l = 0; l < NCONV; l++) {
        k_table<<<TBL, FCO>>>(adw1 + l * BINS, adb1 + l * BINS,
                              adw2 + l * BINS * BINS, adb2 + l * BINS,
                              adal + l, adlut + l * BINS * AFL,
                              fcW + l * (3 * AFL) * FCO, fcb + l * FCO);
        k_proj<<<N_NODES / PROJ_ROWS, 256>>>(fcW + l * (3 * AFL) * FCO);
        k_edgeC<<<EGRID, 256>>>();
        k_red1<<<FCO, 256>>>(bn1g + l * FCO, bn1b + l * FCO);
        k_edgeD<<<DGRID, 256>>>();
        k_red2<<<AFL, 256>>>(bn2g + l * AFL, bn2b + l * AFL);
        k_update_pool<<<N_NODES / PB, 256>>>(ppW, ppb, out, bs);
    }
}

// round 14
// speedup vs baseline: 1.0723x; 1.0602x over previous
#include <cuda_runtime.h>
#include <cuda_bf16.h>
#include <cstdint>

#define N_NODES 51200
#define N_EDGES 614400
#define ORIG    92
#define AFL     64
#define BINS    100
#define NCONV   3
#define TBL     128
#define FCO     128      // 2*AFL
#define EPS_BN  1e-5f
#define EGRID   1024
#define DGRID   1024
#define PROJ_ROWS 64
#define HPAD    68
#define PB      64
#define HT_PAD  68
#define KC      32

typedef unsigned long long u64;
__device__ __forceinline__ u64 pack2(float lo, float hi) {
    u64 r; asm("mov.b64 %0, {%1, %2};" : "=l"(r) : "f"(lo), "f"(hi)); return r;
}
__device__ __forceinline__ void unpack2(u64 v, float& lo, float& hi) {
    asm("mov.b64 {%0, %1}, %2;" : "=f"(lo), "=f"(hi) : "l"(v));
}
__device__ __forceinline__ u64 fma2(u64 a, u64 b, u64 c) {
    u64 d; asm("fma.rn.f32x2 %0, %1, %2, %3;" : "=l"(d) : "l"(a), "l"(b), "l"(c));
    return d;
}
__device__ __forceinline__ void cp_async16(uint32_t saddr, const void* gptr) {
    asm volatile("cp.async.cg.shared.global [%0], [%1], 16;"
                 :: "r"(saddr), "l"(gptr));
}
__device__ __forceinline__ void cp_commit() {
    asm volatile("cp.async.commit_group;" ::: "memory");
}
__device__ __forceinline__ void cp_wait1() {
    asm volatile("cp.async.wait_group 1;" ::: "memory");
}
__device__ __forceinline__ void cp_wait0() {
    asm volatile("cp.async.wait_group 0;" ::: "memory");
}

// ---------------- device scratch (static, no allocations) ----------------
__device__ float g_h[N_NODES * AFL];
__device__ float g_Zd[N_NODES * FCO];
__device__ float g_Zs[N_NODES * FCO];
__device__ float g_T[TBL * FCO];
__device__ float g_aggr[N_NODES * AFL];
__device__ float g_part1[EGRID * 256];
__device__ float g_part2[DGRID * 128];
__device__ float g_bn1sc[FCO], g_bn1sh[FCO];
__device__ float g_bn2sc[AFL], g_bn2sh[AFL];
__device__ int   g_cnt[N_NODES];              // zero-init; re-zeroed by k_scan
__device__ int   g_segstart[N_NODES + 1];
__device__ int   g_off[N_NODES];
__device__ int   g_psrc[N_EDGES];
__device__ int   g_pdst[N_EDGES];
__device__ float g_pattr[N_EDGES];

// ---------------- edge sort ----------------
__global__ void __launch_bounds__(1024) k_hist(const int* __restrict__ ei,
                                               float* __restrict__ out, int osz) {
    int e = blockIdx.x * blockDim.x + threadIdx.x;
    if (e < osz) out[e] = 0.f;
    if (e < N_EDGES) atomicAdd(&g_cnt[ei[N_EDGES + e]], 1);
}

__global__ void __launch_bounds__(1024) k_scan() {
    __shared__ int wsum[32];
    __shared__ int carry;
    int tid = threadIdx.x;
    int lane = tid & 31, wid = tid >> 5;
    if (tid == 0) carry = 0;
    __syncthreads();
    for (int base = 0; base < N_NODES; base += 1024) {
        int v = g_cnt[base + tid];
        g_cnt[base + tid] = 0;
        int x = v;
#pragma unroll
        for (int o = 1; o < 32; o <<= 1) {
            int t = __shfl_up_sync(0xffffffffu, x, o);
            if (lane >= o) x += t;
        }
        if (lane == 31) wsum[wid] = x;
        __syncthreads();
        if (wid == 0) {
            int sv = wsum[lane];
#pragma unroll
            for (int o = 1; o < 32; o <<= 1) {
                int t = __shfl_up_sync(0xffffffffu, sv, o);
                if (lane >= o) sv += t;
            }
            wsum[lane] = sv;
        }
        __syncthreads();
        int woff = (wid > 0) ? wsum[wid - 1] : 0;
        int ex = carry + woff + x - v;
        g_segstart[base + tid] = ex;
        g_off[base + tid] = ex;
        __syncthreads();
        if (tid == 0) carry += wsum[31];
        __syncthreads();
    }
    if (tid == 0) g_segstart[N_NODES] = N_EDGES;
}

__global__ void __launch_bounds__(1024) k_scatter(const int* __restrict__ ei,
                                                  const float* __restrict__ ea) {
    int e = blockIdx.x * blockDim.x + threadIdx.x;
    if (e < N_EDGES) {
        int dst = ei[N_EDGES + e];
        int pos = atomicAdd(&g_off[dst], 1);
        g_psrc[pos] = ei[e];
        g_pdst[pos] = dst;
        g_pattr[pos] = ea[e];
    }
}

// ---------------- shared pool helper (scalar R11 form) ----------------
__device__ __forceinline__ void pool_tile(
    const float* __restrict__ ppWs, const float* __restrict__ hsT,
    float* __restrict__ red, const float* __restrict__ ppb,
    float* __restrict__ out, int n0, int numAtom, int tx, int ty, int tid)
{
    const float4* W4 = reinterpret_cast<const float4*>(ppWs);
    const float4* H4 = reinterpret_cast<const float4*>(hsT);
    float4 pb = *reinterpret_cast<const float4*>(ppb + 4 * tx);
    float4 p0 = pb, p1 = pb, p2 = pb, p3 = pb;
#pragma unroll 8
    for (int k = 0; k < AFL; k++) {
        float4 w4 = W4[k * 16 + tx];
        float4 h4 = H4[k * (HT_PAD / 4) + ty];
        p0.x = fmaf(h4.x, w4.x, p0.x); p0.y = fmaf(h4.x, w4.y, p0.y);
        p0.z = fmaf(h4.x, w4.z, p0.z); p0.w = fmaf(h4.x, w4.w, p0.w);
        p1.x = fmaf(h4.y, w4.x, p1.x); p1.y = fmaf(h4.y, w4.y, p1.y);
        p1.z = fmaf(h4.y, w4.z, p1.z); p1.w = fmaf(h4.y, w4.w, p1.w);
        p2.x = fmaf(h4.z, w4.x, p2.x); p2.y = fmaf(h4.z, w4.y, p2.y);
        p2.z = fmaf(h4.z, w4.z, p2.z); p2.w = fmaf(h4.z, w4.w, p2.w);
        p3.x = fmaf(h4.w, w4.x, p3.x); p3.y = fmaf(h4.w, w4.y, p3.y);
        p3.z = fmaf(h4.w, w4.z, p3.z); p3.w = fmaf(h4.w, w4.w, p3.w);
    }
    float4 pv[4] = {p0, p1, p2, p3};
    float4 val[4];
#pragma unroll
    for (int i = 0; i < 4; i++) {
        float4 p = pv[i];
        float m = fmaxf(fmaxf(p.x, p.y), fmaxf(p.z, p.w));
#pragma unroll
        for (int o = 1; o < 16; o <<= 1)
            m = fmaxf(m, __shfl_xor_sync(0xffffffffu, m, o));
        float4 e;
        e.x = expf(p.x - m); e.y = expf(p.y - m);
        e.z = expf(p.z - m); e.w = expf(p.w - m);
        float s = (e.x + e.y) + (e.z + e.w);
#pragma unroll
        for (int o = 1; o < 16; o <<= 1)
            s += __shfl_xor_sync(0xffffffffu, s, o);
        float inv = 1.f / s;
        val[i] = make_float4(e.x * inv, e.y * inv, e.z * inv, e.w * inv);
    }
    bool same = (n0 / numAtom) == ((n0 + PB - 1) / numAtom);
    if (same) {
        float4 cs;
        cs.x = (val[0].x + val[1].x) + (val[2].x + val[3].x);
        cs.y = (val[0].y + val[1].y) + (val[2].y + val[3].y);
        cs.z = (val[0].z + val[1].z) + (val[2].z + val[3].z);
        cs.w = (val[0].w + val[1].w) + (val[2].w + val[3].w);
        *reinterpret_cast<float4*>(&red[ty * 64 + 4 * tx]) = cs;
        __syncthreads();
        if (tid < 64) {
            float s = 0.f;
#pragma unroll
            for (int r = 0; r < 16; r++) s += red[r * 64 + tid];
            atomicAdd(&out[(n0 / numAtom) * AFL + tid], s);
        }
    } else {
#pragma unroll
        for (int i = 0; i < 4; i++) {
            int node = n0 + 4 * ty + i;
            int cry = node / numAtom;
            atomicAdd(&out[cry * AFL + 4 * tx + 0], val[i].x);
            atomicAdd(&out[cry * AFL + 4 * tx + 1], val[i].y);
            atomicAdd(&out[cry * AFL + 4 * tx + 2], val[i].z);
            atomicAdd(&out[cry * AFL + 4 * tx + 3], val[i].w);
        }
    }
}

// ---------------- embedding + initial pooling (scalar R11 form) ----------------
__global__ void __launch_bounds__(256) k_embed_pool(
    const float* __restrict__ x, const float* __restrict__ att,
    const float* __restrict__ W, const float* __restrict__ b,
    const float* __restrict__ ppW, const float* __restrict__ ppb,
    float* __restrict__ out, const int* __restrict__ bs)
{
    __shared__ float sbuf[KC * AFL + KC * HT_PAD];
    __shared__ float hsT[AFL * HT_PAD];
    __shared__ float red[16 * AFL];
    float* Wc = sbuf;
    float* xsT = sbuf + KC * AFL;
    int tid = threadIdx.x;
    int tx = tid & 15, ty = tid >> 4;
    int n0 = blockIdx.x * PB;

    float4 b4 = *reinterpret_cast<const float4*>(b + 4 * tx);
    float4 a0 = b4, a1 = b4, a2 = b4, a3 = b4;

    for (int kc = 0; kc < ORIG; kc += KC) {
        int kl = min(KC, ORIG - kc);
        __syncthreads();
        for (int i = tid; i < kl * AFL; i += 256) Wc[i] = W[kc * AFL + i];
        for (int idx = tid; idx < PB * KC; idx += 256) {
            int n = idx >> 5, k = idx & 31;
            if (k < kl)
                xsT[k * HT_PAD + n] = x[(size_t)(n0 + n) * ORIG + kc + k] * att[kc + k];
        }
        __syncthreads();
        const float4* Wc4 = reinterpret_cast<const float4*>(Wc);
        const float4* X4 = reinterpret_cast<const float4*>(xsT);
#pragma unroll 4
        for (int k = 0; k < kl; k++) {
            float4 w4 = Wc4[k * 16 + tx];
            float4 h4 = X4[k * (HT_PAD / 4) + ty];
            a0.x = fmaf(h4.x, w4.x, a0.x); a0.y = fmaf(h4.x, w4.y, a0.y);
            a0.z = fmaf(h4.x, w4.z, a0.z); a0.w = fmaf(h4.x, w4.w, a0.w);
            a1.x = fmaf(h4.y, w4.x, a1.x); a1.y = fmaf(h4.y, w4.y, a1.y);
            a1.z = fmaf(h4.y, w4.z, a1.z); a1.w = fmaf(h4.y, w4.w, a1.w);
            a2.x = fmaf(h4.z, w4.x, a2.x); a2.y = fmaf(h4.z, w4.y, a2.y);
            a2.z = fmaf(h4.z, w4.z, a2.z); a2.w = fmaf(h4.z, w4.w, a2.w);
            a3.x = fmaf(h4.w, w4.x, a3.x); a3.y = fmaf(h4.w, w4.y, a3.y);
            a3.z = fmaf(h4.w, w4.z, a3.z); a3.w = fmaf(h4.w, w4.w, a3.w);
        }
    }
    float4 av[4] = {a0, a1, a2, a3};
#pragma unroll
    for (int i = 0; i < 4; i++) {
        int node = n0 + 4 * ty + i;
        *reinterpret_cast<float4*>(&g_h[(size_t)node * AFL + 4 * tx]) = av[i];
        hsT[(4 * tx + 0) * HT_PAD + 4 * ty + i] = av[i].x;
        hsT[(4 * tx + 1) * HT_PAD + 4 * ty + i] = av[i].y;
        hsT[(4 * tx + 2) * HT_PAD + 4 * ty + i] = av[i].z;
        hsT[(4 * tx + 3) * HT_PAD + 4 * ty + i] = av[i].w;
    }
    __syncthreads();
    for (int i = tid; i < AFL * AFL; i += 256) sbuf[i] = ppW[i];
    __syncthreads();
    int numAtom = N_NODES / bs[0];
    pool_tile(sbuf, hsT, red, ppb, out, n0, numAtom, tx, ty, tid);
}

// ---------------- update + pooling (scalar R11 form) ----------------
__global__ void __launch_bounds__(256) k_update_pool(
    const float* __restrict__ ppW, const float* __restrict__ ppb,
    float* __restrict__ out, const int* __restrict__ bs)
{
    __shared__ float ppWs[AFL * AFL];
    __shared__ float hsT[AFL * HT_PAD];
    __shared__ float red[16 * AFL];
    int tid = threadIdx.x;
    int tx = tid & 15, ty = tid >> 4;
    int n0 = blockIdx.x * PB;

    for (int i = tid; i < AFL * AFL; i += 256) ppWs[i] = ppW[i];
    for (int idx = tid; idx < PB * 16; idx += 256) {
        int n = idx >> 4, c4 = idx & 15;
        size_t base = (size_t)(n0 + n) * AFL + 4 * c4;
        float4 h4 = *reinterpret_cast<const float4*>(&g_h[base]);
        float4 g4 = *reinterpret_cast<const float4*>(&g_aggr[base]);
        float4 sc = reinterpret_cast<const float4*>(g_bn2sc)[c4];
        float4 sh = reinterpret_cast<const float4*>(g_bn2sh)[c4];
        float4 up;
        up.x = fmaxf(h4.x + fmaf(g4.x, sc.x, sh.x), 0.f);
        up.y = fmaxf(h4.y + fmaf(g4.y, sc.y, sh.y), 0.f);
        up.z = fmaxf(h4.z + fmaf(g4.z, sc.z, sh.z), 0.f);
        up.w = fmaxf(h4.w + fmaf(g4.w, sc.w, sh.w), 0.f);
        *reinterpret_cast<float4*>(&g_h[base]) = up;
        hsT[(4 * c4 + 0) * HT_PAD + n] = up.x;
        hsT[(4 * c4 + 1) * HT_PAD + n] = up.y;
        hsT[(4 * c4 + 2) * HT_PAD + n] = up.z;
        hsT[(4 * c4 + 3) * HT_PAD + n] = up.w;
    }
    __syncthreads();
    int numAtom = N_NODES / bs[0];
    pool_tile(ppWs, hsT, red, ppb, out, n0, numAtom, tx, ty, tid);
}

// ---------------- fused table ----------------
__global__ void __launch_bounds__(FCO) k_table(
    const float* __restrict__ w1, const float* __restrict__ b1,
    const float* __restrict__ w2, const float* __restrict__ b2,
    const float* __restrict__ alpha, const float* __restrict__ lut,
    const float* __restrict__ fcW, const float* __restrict__ fcb)
{
    __shared__ float v2[BINS];
    __shared__ float p[BINS];
    __shared__ float q[AFL];
    __shared__ float redA[4];
    __shared__ float redB[4];
    int tid = threadIdx.x;
    float a = (float)blockIdx.x / (float)(TBL - 1);
    if (tid < BINS) {
        float v = fmaf(a, w1[tid], b1[tid]);
        v2[tid] = v > 0.f ? v : 0.01f * v;
    }
    __syncthreads();
    float v3 = -3.0e38f;
    if (tid < BINS) {
        float acc = fmaf(alpha[0], v2[tid], b2[tid]);
#pragma unroll 4
        for (int k = 0; k < BINS; k++) acc = fmaf(v2[k], w2[k * BINS + tid], acc);
        v3 = acc;
    }
    float m = v3;
#pragma unroll
    for (int o = 16; o; o >>= 1) m = fmaxf(m, __shfl_xor_sync(0xffffffffu, m, o));
    if ((tid & 31) == 0) redA[tid >> 5] = m;
    __syncthreads();
    m = fmaxf(fmaxf(redA[0], redA[1]), fmaxf(redA[2], redA[3]));
    float ex = (tid < BINS) ? expf(v3 - m) : 0.f;
    float s = ex;
#pragma unroll
    for (int o = 16; o; o >>= 1) s += __shfl_xor_sync(0xffffffffu, s, o);
    if ((tid & 31) == 0) redB[tid >> 5] = s;
    __syncthreads();
    s = (redB[0] + redB[1]) + (redB[2] + redB[3]);
    float inv = 1.f / s;
    if (tid < BINS) p[tid] = ex * inv;
    __syncthreads();
    if (tid < AFL) {
        float acc = 0.f;
#pragma unroll 4
        for (int j = 0; j < BINS; j++) acc = fmaf(p[j], lut[j * AFL + tid], acc);
        q[tid] = acc;
    }
    __syncthreads();
    float acc = fcb[tid];
#pragma unroll 4
    for (int mm = 0; mm < AFL; mm++)
        acc = fmaf(q[mm], fcW[(2 * AFL + mm) * FCO + tid], acc);
    g_T[blockIdx.x * FCO + tid] = acc;
}

// ---------------- node projections: f32x2 + cp.async double-buffered W ----------------
__global__ void __launch_bounds__(256) k_proj(const float* __restrict__ fcW)
{
    __shared__ float Wsh[2][16 * 256];        // 32 KB double buffer
    __shared__ float hsh[AFL * HPAD];         // 17.4 KB
    int tid = threadIdx.x;
    int tx = tid & 63;
    int ty = tid >> 6;
    int r0 = blockIdx.x * PROJ_ROWS;
    int col = 4 * tx;

    uint32_t wbase[2];
    wbase[0] = (uint32_t)__cvta_generic_to_shared(&Wsh[0][0]);
    wbase[1] = (uint32_t)__cvta_generic_to_shared(&Wsh[1][0]);

    // prefetch W chunk kc into buffer buf (16 KB = 1024 float4, 4 per thread)
    auto prefetch = [&](int kc, int buf) {
#pragma unroll
        for (int q = 0; q < 4; q++) {
            int f = tid + q * 256;            // float4 index
            int kk = f >> 6;                  // k-row within chunk
            int c4 = f & 63;                  // float4 within row of 256 floats
            int h2 = c4 >> 5;                 // 0=Zd half, 1=Zs half
            int c2 = (c4 & 31) * 4;           // float offset within FCO row
            const float* g = &fcW[(size_t)(h2 * AFL + kc * 16 + kk) * FCO + c2];
            cp_async16(wbase[buf] + (uint32_t)f * 16u, g);
        }
        cp_commit();
    };

    prefetch(0, 0);

    for (int i = tid; i < PROJ_ROWS * AFL; i += 256) {
        int r = i >> 6, k = i & 63;
        hsh[k * HPAD + r] = g_h[(size_t)(r0 + r) * AFL + k];
    }

    u64 accP[8][4];
    u64 zero = pack2(0.f, 0.f);
#pragma unroll
    for (int p = 0; p < 8; p++)
#pragma unroll
        for (int c = 0; c < 4; c++) accP[p][c] = zero;

    for (int kc = 0; kc < 4; kc++) {
        int cur = kc & 1;
        __syncthreads();                       // all readers done with buffer we overwrite; hsh ready (kc=0)
        if (kc < 3) {
            prefetch(kc + 1, cur ^ 1);
            cp_wait1();                        // chunk kc's group complete
        } else {
            cp_wait0();
        }
        __syncthreads();                       // cp.async writes visible to all

#pragma unroll
        for (int kk = 0; kk < 16; kk++) {
            float4 w4 = *reinterpret_cast<const float4*>(&Wsh[cur][kk * 256 + col]);
            u64 wd0 = pack2(w4.x, w4.x);
            u64 wd1 = pack2(w4.y, w4.y);
            u64 wd2 = pack2(w4.z, w4.z);
            u64 wd3 = pack2(w4.w, w4.w);
            const u64* hp = reinterpret_cast<const u64*>(
                &hsh[(kc * 16 + kk) * HPAD + ty * 16]);
#pragma unroll
            for (int p = 0; p < 8; p++) {
                u64 h2v = hp[p];
                accP[p][0] = fma2(h2v, wd0, accP[p][0]);
                accP[p][1] = fma2(h2v, wd1, accP[p][1]);
                accP[p][2] = fma2(h2v, wd2, accP[p][2]);
                accP[p][3] = fma2(h2v, wd3, accP[p][3]);
            }
        }
    }
    int half = col >> 7;
    int cc = col & 127;
    float* dst = half ? g_Zs : g_Zd;
#pragma unroll
    for (int p = 0; p < 8; p++) {
        float4 lo4, hi4;
        unpack2(accP[p][0], lo4.x, hi4.x);
        unpack2(accP[p][1], lo4.y, hi4.y);
        unpack2(accP[p][2], lo4.z, hi4.z);
        unpack2(accP[p][3], lo4.w, hi4.w);
        *reinterpret_cast<float4*>(&dst[(size_t)(r0 + ty * 16 + 2 * p) * FCO + cc]) = lo4;
        *reinterpret_cast<float4*>(&dst[(size_t)(r0 + ty * 16 + 2 * p + 1) * FCO + cc]) = hi4;
    }
}

// ---------------- pass C: flat edge-parallel BN1 stats (R8 best) ----------------
__global__ void __launch_bounds__(256) k_edgeC()
{
    __shared__ float sred[8 * 256];
    int tid = threadIdx.x;
    int warp = tid >> 5, lane = tid & 31;
    int gwarp = blockIdx.x * 8 + warp;
    int nwarp = gridDim.x * 8;
    const float4* T4  = reinterpret_cast<const float4*>(g_T);
    const float4* Zd4 = reinterpret_cast<const float4*>(g_Zd);
    const float4* Zs4 = reinterpret_cast<const float4*>(g_Zs);
    float4 ps = {0,0,0,0}, pq = {0,0,0,0};

    for (int e0 = gwarp * 4; e0 < N_EDGES; e0 += nwarp * 4) {
        int4   ss = __ldg(reinterpret_cast<const int4*>(g_psrc + e0));
        int4   dd = __ldg(reinterpret_cast<const int4*>(g_pdst + e0));
        float4 aa = __ldg(reinterpret_cast<const float4*>(g_pattr + e0));
        float4 zs0 = __ldg(Zs4 + (size_t)ss.x * 32 + lane);
        float4 zs1 = __ldg(Zs4 + (size_t)ss.y * 32 + lane);
        float4 zs2 = __ldg(Zs4 + (size_t)ss.z * 32 + lane);
        float4 zs3 = __ldg(Zs4 + (size_t)ss.w * 32 + lane);
        float4 zd0 = __ldg(Zd4 + (size_t)dd.x * 32 + lane);
        float4 zd1 = __ldg(Zd4 + (size_t)dd.y * 32 + lane);
        float4 zd2 = __ldg(Zd4 + (size_t)dd.z * 32 + lane);
        float4 zd3 = __ldg(Zd4 + (size_t)dd.w * 32 + lane);

#define DOEDGE_C(ZD, ZS, A)                                                  \
        {                                                                    \
            float pos = fminf(fmaxf((A) * (float)(TBL - 1), 0.f),            \
                              (float)(TBL - 1));                             \
            int t0 = min((int)pos, TBL - 2);                                 \
            float w = pos - (float)t0;                                       \
            float4 T0 = __ldg(T4 + t0 * 32 + lane);                          \
            float4 T1 = __ldg(T4 + (t0 + 1) * 32 + lane);                    \
            float zx = ZD.x + ZS.x + fmaf(w, T1.x - T0.x, T0.x);             \
            float zy = ZD.y + ZS.y + fmaf(w, T1.y - T0.y, T0.y);             \
            float zz = ZD.z + ZS.z + fmaf(w, T1.z - T0.z, T0.z);             \
            float zw = ZD.w + ZS.w + fmaf(w, T1.w - T0.w, T0.w);             \
            ps.x += zx; ps.y += zy; ps.z += zz; ps.w += zw;                  \
            pq.x = fmaf(zx, zx, pq.x); pq.y = fmaf(zy, zy, pq.y);            \
            pq.z = fmaf(zz, zz, pq.z); pq.w = fmaf(zw, zw, pq.w);            \
        }
        DOEDGE_C(zd0, zs0, aa.x)
        DOEDGE_C(zd1, zs1, aa.y)
        DOEDGE_C(zd2, zs2, aa.z)
        DOEDGE_C(zd3, zs3, aa.w)
#undef DOEDGE_C
    }
    {
        float* sb = &sred[warp * 256];
        int c4 = lane * 4;
        sb[c4 + 0] = ps.x; sb[c4 + 1] = ps.y; sb[c4 + 2] = ps.z; sb[c4 + 3] = ps.w;
        sb[128 + c4 + 0] = pq.x; sb[128 + c4 + 1] = pq.y;
        sb[128 + c4 + 2] = pq.z; sb[128 + c4 + 3] = pq.w;
    }
    __syncthreads();
    float v = 0.f;
#pragma unroll
    for (int w = 0; w < 8; w++) v += sred[w * 256 + tid];
    g_part1[blockIdx.x * 256 + tid] = v;
}

__global__ void __launch_bounds__(256) k_red1(
    const float* __restrict__ g1, const float* __restrict__ b1)
{
    __shared__ float ssum[256], ssq[256];
    int c = blockIdx.x;
    int t = threadIdx.x;
    float s = 0.f, q = 0.f;
    for (int r = t; r < EGRID; r += 256) {
        s += g_part1[r * 256 + c];
        q += g_part1[r * 256 + 128 + c];
    }
    ssum[t] = s; ssq[t] = q;
    __syncthreads();
    for (int o = 128; o; o >>= 1) {
        if (t < o) { ssum[t] += ssum[t + o]; ssq[t] += ssq[t + o]; }
        __syncthreads();
    }
    if (t == 0) {
        const float invE = 1.f / (float)N_EDGES;
        float mu = ssum[0] * invE;
        float var = ssq[0] * invE - mu * mu;
        float sc = rsqrtf(var + EPS_BN) * g1[c];
        g_bn1sc[c] = sc;
        g_bn1sh[c] = fmaf(-mu, sc, b1[c]);
    }
}

// ---------------- pass D: segment 4-wide (final form) ----------------
__global__ void __launch_bounds__(256) k_edgeD()
{
    __shared__ float sred[8 * 128];
    int tid = threadIdx.x;
    int warp = tid >> 5, lane = tid & 31;
    int cl = lane & 15, eh = lane >> 4;
    int gw = blockIdx.x * 8 + warp;
    int nw = gridDim.x * 8;
    const float4* T4 = reinterpret_cast<const float4*>(g_T);
    float4 sc0 = reinterpret_cast<const float4*>(g_bn1sc)[cl];
    float4 sc1 = reinterpret_cast<const float4*>(g_bn1sc)[16 + cl];
    float4 sh0 = reinterpret_cast<const float4*>(g_bn1sh)[cl];
    float4 sh1 = reinterpret_cast<const float4*>(g_bn1sh)[16 + cl];
    float4 ps = {0,0,0,0}, pq = {0,0,0,0};

    for (int n = gw; n < N_NODES; n += nw) {
        int beg = g_segstart[n], end = g_segstart[n + 1];
        float4 acc = {0,0,0,0};
        if (beg < end) {
            const float4* zdp = reinterpret_cast<const float4*>(&g_Zd[(size_t)n * FCO]);
            float4 zd0 = __ldg(zdp + cl), zd1 = __ldg(zdp + 16 + cl);

            auto doedge = [&](const float4& zs0, const float4& zs1, float a) {
                float pos = fminf(fmaxf(a * (float)(TBL - 1), 0.f), (float)(TBL - 1));
                int t0 = min((int)pos, TBL - 2);
                float w = pos - (float)t0;
                float4 T0l = __ldg(T4 + t0 * 32 + cl);
                float4 T0h = __ldg(T4 + t0 * 32 + 16 + cl);
                float4 T1l = __ldg(T4 + (t0 + 1) * 32 + cl);
                float4 T1h = __ldg(T4 + (t0 + 1) * 32 + 16 + cl);
                float4 z0, z1;
                z0.x = zd0.x + zs0.x + fmaf(w, T1l.x - T0l.x, T0l.x);
                z0.y = zd0.y + zs0.y + fmaf(w, T1l.y - T0l.y, T0l.y);
                z0.z = zd0.z + zs0.z + fmaf(w, T1l.z - T0l.z, T0l.z);
                z0.w = zd0.w + zs0.w + fmaf(w, T1l.w - T0l.w, T0l.w);
                z1.x = zd1.x + zs1.x + fmaf(w, T1h.x - T0h.x, T0h.x);
                z1.y = zd1.y + zs1.y + fmaf(w, T1h.y - T0h.y, T0h.y);
                z1.z = zd1.z + zs1.z + fmaf(w, T1h.z - T0h.z, T0h.z);
                z1.w = zd1.w + zs1.w + fmaf(w, T1h.w - T0h.w, T0h.w);
                float fx = fmaxf(fmaf(z0.x, sc0.x, sh0.x), 0.f);
                float fy = fmaxf(fmaf(z0.y, sc0.y, sh0.y), 0.f);
                float fz = fmaxf(fmaf(z0.z, sc0.z, sh0.z), 0.f);
                float fw = fmaxf(fmaf(z0.w, sc0.w, sh0.w), 0.f);
                float gx = fmaxf(fmaf(z1.x, sc1.x, sh1.x), 0.f);
                float gy = fmaxf(fmaf(z1.y, sc1.y, sh1.y), 0.f);
                float gz = fmaxf(fmaf(z1.z, sc1.z, sh1.z), 0.f);
                float gw2 = fmaxf(fmaf(z1.w, sc1.w, sh1.w), 0.f);
                acc.x = fmaf(fx, gx, acc.x);
                acc.y = fmaf(fy, gy, acc.y);
                acc.z = fmaf(fz, gz, acc.z);
                acc.w = fmaf(fw, gw2, acc.w);
            };

            for (int base = beg; base < end; base += 32) {
                int e = base + lane;
                int sv = 0; float av = 0.f;
                if (e < end) { sv = g_psrc[e]; av = g_pattr[e]; }
                int cnt = min(32, end - base);
                int j = 0;
                for (; j + 4 <= cnt; j += 4) {
                    int iA = j + eh, iB = j + 2 + eh;
                    int sA = __shfl_sync(0xffffffffu, sv, iA);
                    int sB = __shfl_sync(0xffffffffu, sv, iB);
                    float aA = __shfl_sync(0xffffffffu, av, iA);
                    float aB = __shfl_sync(0xffffffffu, av, iB);
                    const float4* zA = reinterpret_cast<const float4*>(&g_Zs[(size_t)sA * FCO]);
                    const float4* zB = reinterpret_cast<const float4*>(&g_Zs[(size_t)sB * FCO]);
                    float4 zA0 = __ldg(zA + cl), zA1 = __ldg(zA + 16 + cl);
                    float4 zB0 = __ldg(zB + cl), zB1 = __ldg(zB + 16 + cl);
                    doedge(zA0, zA1, aA);
                    doedge(zB0, zB1, aB);
                }
                for (; j + 2 <= cnt; j += 2) {
                    int iA = j + eh;
                    int sA = __shfl_sync(0xffffffffu, sv, iA);
                    float aA = __shfl_sync(0xffffffffu, av, iA);
                    const float4* zA = reinterpret_cast<const float4*>(&g_Zs[(size_t)sA * FCO]);
                    float4 zA0 = __ldg(zA + cl), zA1 = __ldg(zA + 16 + cl);
                    doedge(zA0, zA1, aA);
                }
                if (j < cnt) {
                    int sA = __shfl_sync(0xffffffffu, sv, j);
                    float aA = __shfl_sync(0xffffffffu, av, j);
                    if (eh == 0) {
                        const float4* zA = reinterpret_cast<const float4*>(&g_Zs[(size_t)sA * FCO]);
                        float4 zA0 = __ldg(zA + cl), zA1 = __ldg(zA + 16 + cl);
                        doedge(zA0, zA1, aA);
                    }
                }
            }
        }
        acc.x += __shfl_down_sync(0xffffffffu, acc.x, 16);
        acc.y += __shfl_down_sync(0xffffffffu, acc.y, 16);
        acc.z += __shfl_down_sync(0xffffffffu, acc.z, 16);
        acc.w += __shfl_down_sync(0xffffffffu, acc.w, 16);
        if (eh == 0) {
            reinterpret_cast<float4*>(&g_aggr[(size_t)n * AFL])[cl] = acc;
            ps.x += acc.x; ps.y += acc.y; ps.z += acc.z; ps.w += acc.w;
            pq.x = fmaf(acc.x, acc.x, pq.x); pq.y = fmaf(acc.y, acc.y, pq.y);
            pq.z = fmaf(acc.z, acc.z, pq.z); pq.w = fmaf(acc.w, acc.w, pq.w);
        }
    }
    if (eh == 0) {
        float* sb = &sred[warp * 128];
        int c4 = cl * 4;
        sb[c4 + 0] = ps.x; sb[c4 + 1] = ps.y; sb[c4 + 2] = ps.z; sb[c4 + 3] = ps.w;
        sb[64 + c4 + 0] = pq.x; sb[64 + c4 + 1] = pq.y; sb[64 + c4 + 2] = pq.z; sb[64 + c4 + 3] = pq.w;
    }
    __syncthreads();
    if (tid < 128) {
        float v = 0.f;
#pragma unroll
        for (int w = 0; w < 8; w++) v += sred[w * 128 + tid];
        g_part2[blockIdx.x * 128 + tid] = v;
    }
}

__global__ void __launch_bounds__(256) k_red2(
    const float* __restrict__ g2, const float* __restrict__ b2)
{
    __shared__ float ssum[256], ssq[256];
    int c = blockIdx.x;
    int t = threadIdx.x;
    float s = 0.f, q = 0.f;
    for (int r = t; r < DGRID; r += 256) {
        s += g_part2[r * 128 + c];
        q += g_part2[r * 128 + 64 + c];
    }
    ssum[t] = s; ssq[t] = q;
    __syncthreads();
    for (int o = 128; o; o >>= 1) {
        if (t < o) { ssum[t] += ssum[t + o]; ssq[t] += ssq[t + o]; }
        __syncthreads();
    }
    if (t == 0) {
        const float invN = 1.f / (float)N_NODES;
        float mu = ssum[0] * invN;
        float var = ssq[0] * invN - mu * mu;
        float sc = rsqrtf(var + EPS_BN) * g2[c];
        g_bn2sc[c] = sc;
        g_bn2sh[c] = fmaf(-mu, sc, b2[c]);
    }
}

// ---------------- launch ----------------
extern "C" void kernel_launch(void* const* d_in, const int* in_sizes, int n_in,
                              void* d_out, int out_size)
{
    const float* x     = (const float*)d_in[0];
    const int*   ei    = (const int*)  d_in[1];
    const float* ea    = (const float*)d_in[2];
    const int*   bs    = (const int*)  d_in[3];
    const float* att   = (const float*)d_in[4];
    const float* embW  = (const float*)d_in[5];
    const float* embb  = (const float*)d_in[6];
    const float* adw1  = (const float*)d_in[7];
    const float* adb1  = (const float*)d_in[8];
    const float* adw2  = (const float*)d_in[9];
    const float* adb2  = (const float*)d_in[10];
    const float* adal  = (const float*)d_in[11];
    const float* adlut = (const float*)d_in[12];
    const float* fcW   = (const float*)d_in[13];
    const float* fcb   = (const float*)d_in[14];
    const float* bn1g  = (const float*)d_in[15];
    const float* bn1b  = (const float*)d_in[16];
    const float* bn2g  = (const float*)d_in[17];
    const float* bn2b  = (const float*)d_in[18];
    const float* ppW   = (const float*)d_in[19];
    const float* ppb   = (const float*)d_in[20];
    float* out = (float*)d_out;

    k_hist<<<N_EDGES / 1024, 1024>>>(ei, out, out_size);
    k_scan<<<1, 1024>>>();
    k_scatter<<<N_EDGES / 1024, 1024>>>(ei, ea);
    k_embed_pool<<<N_NODES / PB, 256>>>(x, att, embW, embb, ppW, ppb, out, bs);

    for (int l = 0; l < NCONV; l++) {
        k_table<<<TBL, FCO>>>(adw1 + l * BINS, adb1 + l * BINS,
                              adw2 + l * BINS * BINS, adb2 + l * BINS,
                              adal + l, adlut + l * BINS * AFL,
                              fcW + l * (3 * AFL) * FCO, fcb + l * FCO);
        k_proj<<<N_NODES / PROJ_ROWS, 256>>>(fcW + l * (3 * AFL) * FCO);
        k_edgeC<<<EGRID, 256>>>();
        k_red1<<<FCO, 256>>>(bn1g + l * FCO, bn1b + l * FCO);
        k_edgeD<<<DGRID, 256>>>();
        k_red2<<<AFL, 256>>>(bn2g + l * AFL, bn2b + l * AFL);
        k_update_pool<<<N_NODES / PB, 256>>>(ppW, ppb, out, bs);
    }
}

// round 15
// speedup vs baseline: 1.1264x; 1.0505x over previous
#include <cuda_runtime.h>
#include <cuda_bf16.h>
#include <cstdint>

#define N_NODES 51200
#define N_EDGES 614400
#define ORIG    92
#define AFL     64
#define BINS    100
#define NCONV   3
#define TBL     128
#define FCO     128      // 2*AFL
#define EPS_BN  1e-5f
#define EGRID   1024
#define DGRID   1024
#define PROJ_ROWS 64
#define NPROJ   (N_NODES / PROJ_ROWS)     // 800
#define HPAD    68
#define PB      64
#define HT_PAD  68
#define KC      32

typedef unsigned long long u64;
__device__ __forceinline__ u64 pack2(float lo, float hi) {
    u64 r; asm("mov.b64 %0, {%1, %2};" : "=l"(r) : "f"(lo), "f"(hi)); return r;
}
__device__ __forceinline__ void unpack2(u64 v, float& lo, float& hi) {
    asm("mov.b64 {%0, %1}, %2;" : "=f"(lo), "=f"(hi) : "l"(v));
}
__device__ __forceinline__ u64 fma2(u64 a, u64 b, u64 c) {
    u64 d; asm("fma.rn.f32x2 %0, %1, %2, %3;" : "=l"(d) : "l"(a), "l"(b), "l"(c));
    return d;
}
__device__ __forceinline__ void cp_async16(uint32_t saddr, const void* gptr) {
    asm volatile("cp.async.cg.shared.global [%0], [%1], 16;"
                 :: "r"(saddr), "l"(gptr));
}
__device__ __forceinline__ void cp_commit() {
    asm volatile("cp.async.commit_group;" ::: "memory");
}
__device__ __forceinline__ void cp_wait1() {
    asm volatile("cp.async.wait_group 1;" ::: "memory");
}
__device__ __forceinline__ void cp_wait0() {
    asm volatile("cp.async.wait_group 0;" ::: "memory");
}

// ---------------- device scratch (static, no allocations) ----------------
__device__ float g_h[N_NODES * AFL];
__device__ float g_Zd[N_NODES * FCO];
__device__ float g_Zs[N_NODES * FCO];
__device__ float g_T[TBL * FCO];
__device__ float g_aggr[N_NODES * AFL];
__device__ float g_part1[EGRID * 256];
__device__ float g_part2[DGRID * 128];
__device__ float g_bn1sc[FCO], g_bn1sh[FCO];
__device__ float g_bn2sc[AFL], g_bn2sh[AFL];
__device__ int   g_cnt[N_NODES];              // zero-init; re-zeroed by k_scan
__device__ int   g_segstart[N_NODES + 1];
__device__ int   g_off[N_NODES];
__device__ int   g_psrc[N_EDGES];
__device__ int   g_pdst[N_EDGES];
__device__ float g_pattr[N_EDGES];

// ---------------- edge sort ----------------
__global__ void __launch_bounds__(1024) k_hist(const int* __restrict__ ei,
                                               float* __restrict__ out, int osz) {
    int e = blockIdx.x * blockDim.x + threadIdx.x;
    if (e < osz) out[e] = 0.f;
    if (e < N_EDGES) atomicAdd(&g_cnt[ei[N_EDGES + e]], 1);
}

__global__ void __launch_bounds__(1024) k_scan() {
    __shared__ int wsum[32];
    __shared__ int carry;
    int tid = threadIdx.x;
    int lane = tid & 31, wid = tid >> 5;
    if (tid == 0) carry = 0;
    __syncthreads();
    for (int base = 0; base < N_NODES; base += 1024) {
        int v = g_cnt[base + tid];
        g_cnt[base + tid] = 0;
        int x = v;
#pragma unroll
        for (int o = 1; o < 32; o <<= 1) {
            int t = __shfl_up_sync(0xffffffffu, x, o);
            if (lane >= o) x += t;
        }
        if (lane == 31) wsum[wid] = x;
        __syncthreads();
        if (wid == 0) {
            int sv = wsum[lane];
#pragma unroll
            for (int o = 1; o < 32; o <<= 1) {
                int t = __shfl_up_sync(0xffffffffu, sv, o);
                if (lane >= o) sv += t;
            }
            wsum[lane] = sv;
        }
        __syncthreads();
        int woff = (wid > 0) ? wsum[wid - 1] : 0;
        int ex = carry + woff + x - v;
        g_segstart[base + tid] = ex;
        g_off[base + tid] = ex;
        __syncthreads();
        if (tid == 0) carry += wsum[31];
        __syncthreads();
    }
    if (tid == 0) g_segstart[N_NODES] = N_EDGES;
}

__global__ void __launch_bounds__(1024) k_scatter(const int* __restrict__ ei,
                                                  const float* __restrict__ ea) {
    int e = blockIdx.x * blockDim.x + threadIdx.x;
    if (e < N_EDGES) {
        int dst = ei[N_EDGES + e];
        int pos = atomicAdd(&g_off[dst], 1);
        g_psrc[pos] = ei[e];
        g_pdst[pos] = dst;
        g_pattr[pos] = ea[e];
    }
}

// ---------------- shared pool helper (scalar R11 form) ----------------
__device__ __forceinline__ void pool_tile(
    const float* __restrict__ ppWs, const float* __restrict__ hsT,
    float* __restrict__ red, const float* __restrict__ ppb,
    float* __restrict__ out, int n0, int numAtom, int tx, int ty, int tid)
{
    const float4* W4 = reinterpret_cast<const float4*>(ppWs);
    const float4* H4 = reinterpret_cast<const float4*>(hsT);
    float4 pb = *reinterpret_cast<const float4*>(ppb + 4 * tx);
    float4 p0 = pb, p1 = pb, p2 = pb, p3 = pb;
#pragma unroll 8
    for (int k = 0; k < AFL; k++) {
        float4 w4 = W4[k * 16 + tx];
        float4 h4 = H4[k * (HT_PAD / 4) + ty];
        p0.x = fmaf(h4.x, w4.x, p0.x); p0.y = fmaf(h4.x, w4.y, p0.y);
        p0.z = fmaf(h4.x, w4.z, p0.z); p0.w = fmaf(h4.x, w4.w, p0.w);
        p1.x = fmaf(h4.y, w4.x, p1.x); p1.y = fmaf(h4.y, w4.y, p1.y);
        p1.z = fmaf(h4.y, w4.z, p1.z); p1.w = fmaf(h4.y, w4.w, p1.w);
        p2.x = fmaf(h4.z, w4.x, p2.x); p2.y = fmaf(h4.z, w4.y, p2.y);
        p2.z = fmaf(h4.z, w4.z, p2.z); p2.w = fmaf(h4.z, w4.w, p2.w);
        p3.x = fmaf(h4.w, w4.x, p3.x); p3.y = fmaf(h4.w, w4.y, p3.y);
        p3.z = fmaf(h4.w, w4.z, p3.z); p3.w = fmaf(h4.w, w4.w, p3.w);
    }
    float4 pv[4] = {p0, p1, p2, p3};
    float4 val[4];
#pragma unroll
    for (int i = 0; i < 4; i++) {
        float4 p = pv[i];
        float m = fmaxf(fmaxf(p.x, p.y), fmaxf(p.z, p.w));
#pragma unroll
        for (int o = 1; o < 16; o <<= 1)
            m = fmaxf(m, __shfl_xor_sync(0xffffffffu, m, o));
        float4 e;
        e.x = expf(p.x - m); e.y = expf(p.y - m);
        e.z = expf(p.z - m); e.w = expf(p.w - m);
        float s = (e.x + e.y) + (e.z + e.w);
#pragma unroll
        for (int o = 1; o < 16; o <<= 1)
            s += __shfl_xor_sync(0xffffffffu, s, o);
        float inv = 1.f / s;
        val[i] = make_float4(e.x * inv, e.y * inv, e.z * inv, e.w * inv);
    }
    bool same = (n0 / numAtom) == ((n0 + PB - 1) / numAtom);
    if (same) {
        float4 cs;
        cs.x = (val[0].x + val[1].x) + (val[2].x + val[3].x);
        cs.y = (val[0].y + val[1].y) + (val[2].y + val[3].y);
        cs.z = (val[0].z + val[1].z) + (val[2].z + val[3].z);
        cs.w = (val[0].w + val[1].w) + (val[2].w + val[3].w);
        *reinterpret_cast<float4*>(&red[ty * 64 + 4 * tx]) = cs;
        __syncthreads();
        if (tid < 64) {
            float s = 0.f;
#pragma unroll
            for (int r = 0; r < 16; r++) s += red[r * 64 + tid];
            atomicAdd(&out[(n0 / numAtom) * AFL + tid], s);
        }
    } else {
#pragma unroll
        for (int i = 0; i < 4; i++) {
            int node = n0 + 4 * ty + i;
            int cry = node / numAtom;
            atomicAdd(&out[cry * AFL + 4 * tx + 0], val[i].x);
            atomicAdd(&out[cry * AFL + 4 * tx + 1], val[i].y);
            atomicAdd(&out[cry * AFL + 4 * tx + 2], val[i].z);
            atomicAdd(&out[cry * AFL + 4 * tx + 3], val[i].w);
        }
    }
}

// ---------------- embedding + initial pooling ----------------
__global__ void __launch_bounds__(256) k_embed_pool(
    const float* __restrict__ x, const float* __restrict__ att,
    const float* __restrict__ W, const float* __restrict__ b,
    const float* __restrict__ ppW, const float* __restrict__ ppb,
    float* __restrict__ out, const int* __restrict__ bs)
{
    __shared__ float sbuf[KC * AFL + KC * HT_PAD];
    __shared__ float hsT[AFL * HT_PAD];
    __shared__ float red[16 * AFL];
    float* Wc = sbuf;
    float* xsT = sbuf + KC * AFL;
    int tid = threadIdx.x;
    int tx = tid & 15, ty = tid >> 4;
    int n0 = blockIdx.x * PB;

    float4 b4 = *reinterpret_cast<const float4*>(b + 4 * tx);
    float4 a0 = b4, a1 = b4, a2 = b4, a3 = b4;

    for (int kc = 0; kc < ORIG; kc += KC) {
        int kl = min(KC, ORIG - kc);
        __syncthreads();
        for (int i = tid; i < kl * AFL; i += 256) Wc[i] = W[kc * AFL + i];
        for (int idx = tid; idx < PB * KC; idx += 256) {
            int n = idx >> 5, k = idx & 31;
            if (k < kl)
                xsT[k * HT_PAD + n] = x[(size_t)(n0 + n) * ORIG + kc + k] * att[kc + k];
        }
        __syncthreads();
        const float4* Wc4 = reinterpret_cast<const float4*>(Wc);
        const float4* X4 = reinterpret_cast<const float4*>(xsT);
#pragma unroll 4
        for (int k = 0; k < kl; k++) {
            float4 w4 = Wc4[k * 16 + tx];
            float4 h4 = X4[k * (HT_PAD / 4) + ty];
            a0.x = fmaf(h4.x, w4.x, a0.x); a0.y = fmaf(h4.x, w4.y, a0.y);
            a0.z = fmaf(h4.x, w4.z, a0.z); a0.w = fmaf(h4.x, w4.w, a0.w);
            a1.x = fmaf(h4.y, w4.x, a1.x); a1.y = fmaf(h4.y, w4.y, a1.y);
            a1.z = fmaf(h4.y, w4.z, a1.z); a1.w = fmaf(h4.y, w4.w, a1.w);
            a2.x = fmaf(h4.z, w4.x, a2.x); a2.y = fmaf(h4.z, w4.y, a2.y);
            a2.z = fmaf(h4.z, w4.z, a2.z); a2.w = fmaf(h4.z, w4.w, a2.w);
            a3.x = fmaf(h4.w, w4.x, a3.x); a3.y = fmaf(h4.w, w4.y, a3.y);
            a3.z = fmaf(h4.w, w4.z, a3.z); a3.w = fmaf(h4.w, w4.w, a3.w);
        }
    }
    float4 av[4] = {a0, a1, a2, a3};
#pragma unroll
    for (int i = 0; i < 4; i++) {
        int node = n0 + 4 * ty + i;
        *reinterpret_cast<float4*>(&g_h[(size_t)node * AFL + 4 * tx]) = av[i];
        hsT[(4 * tx + 0) * HT_PAD + 4 * ty + i] = av[i].x;
        hsT[(4 * tx + 1) * HT_PAD + 4 * ty + i] = av[i].y;
        hsT[(4 * tx + 2) * HT_PAD + 4 * ty + i] = av[i].z;
        hsT[(4 * tx + 3) * HT_PAD + 4 * ty + i] = av[i].w;
    }
    __syncthreads();
    for (int i = tid; i < AFL * AFL; i += 256) sbuf[i] = ppW[i];
    __syncthreads();
    int numAtom = N_NODES / bs[0];
    pool_tile(sbuf, hsT, red, ppb, out, n0, numAtom, tx, ty, tid);
}

// ---------------- update + pooling ----------------
__global__ void __launch_bounds__(256) k_update_pool(
    const float* __restrict__ ppW, const float* __restrict__ ppb,
    float* __restrict__ out, const int* __restrict__ bs)
{
    __shared__ float ppWs[AFL * AFL];
    __shared__ float hsT[AFL * HT_PAD];
    __shared__ float red[16 * AFL];
    int tid = threadIdx.x;
    int tx = tid & 15, ty = tid >> 4;
    int n0 = blockIdx.x * PB;

    for (int i = tid; i < AFL * AFL; i += 256) ppWs[i] = ppW[i];
    for (int idx = tid; idx < PB * 16; idx += 256) {
        int n = idx >> 4, c4 = idx & 15;
        size_t base = (size_t)(n0 + n) * AFL + 4 * c4;
        float4 h4 = *reinterpret_cast<const float4*>(&g_h[base]);
        float4 g4 = *reinterpret_cast<const float4*>(&g_aggr[base]);
        float4 sc = reinterpret_cast<const float4*>(g_bn2sc)[c4];
        float4 sh = reinterpret_cast<const float4*>(g_bn2sh)[c4];
        float4 up;
        up.x = fmaxf(h4.x + fmaf(g4.x, sc.x, sh.x), 0.f);
        up.y = fmaxf(h4.y + fmaf(g4.y, sc.y, sh.y), 0.f);
        up.z = fmaxf(h4.z + fmaf(g4.z, sc.z, sh.z), 0.f);
        up.w = fmaxf(h4.w + fmaf(g4.w, sc.w, sh.w), 0.f);
        *reinterpret_cast<float4*>(&g_h[base]) = up;
        hsT[(4 * c4 + 0) * HT_PAD + n] = up.x;
        hsT[(4 * c4 + 1) * HT_PAD + n] = up.y;
        hsT[(4 * c4 + 2) * HT_PAD + n] = up.z;
        hsT[(4 * c4 + 3) * HT_PAD + n] = up.w;
    }
    __syncthreads();
    int numAtom = N_NODES / bs[0];
    pool_tile(ppWs, hsT, red, ppb, out, n0, numAtom, tx, ty, tid);
}

// ---------------- combined: proj (blocks < NPROJ) + table (blocks >= NPROJ) ----------------
__global__ void __launch_bounds__(256) k_projtable(
    const float* __restrict__ fcW,
    const float* __restrict__ w1, const float* __restrict__ b1,
    const float* __restrict__ w2, const float* __restrict__ b2,
    const float* __restrict__ alpha, const float* __restrict__ lut,
    const float* __restrict__ fcb)
{
    __shared__ float smem_all[2 * 16 * 256 + AFL * HPAD];  // 49.4 KB (proj) >> table needs
    int tid = threadIdx.x;

    if (blockIdx.x < NPROJ) {
        // ================= proj body (R14 best) =================
        float* Wsh0 = smem_all;
        float* Wsh1 = smem_all + 16 * 256;
        float* hsh  = smem_all + 2 * 16 * 256;
        int tx = tid & 63;
        int ty = tid >> 6;
        int r0 = blockIdx.x * PROJ_ROWS;
        int col = 4 * tx;

        uint32_t wbase[2];
        wbase[0] = (uint32_t)__cvta_generic_to_shared(Wsh0);
        wbase[1] = (uint32_t)__cvta_generic_to_shared(Wsh1);

        auto prefetch = [&](int kc, int buf) {
#pragma unroll
            for (int q = 0; q < 4; q++) {
                int f = tid + q * 256;
                int kk = f >> 6;
                int c4 = f & 63;
                int h2 = c4 >> 5;
                int c2 = (c4 & 31) * 4;
                const float* g = &fcW[(size_t)(h2 * AFL + kc * 16 + kk) * FCO + c2];
                cp_async16(wbase[buf] + (uint32_t)f * 16u, g);
            }
            cp_commit();
        };

        prefetch(0, 0);

        for (int i = tid; i < PROJ_ROWS * AFL; i += 256) {
            int r = i >> 6, k = i & 63;
            hsh[k * HPAD + r] = g_h[(size_t)(r0 + r) * AFL + k];
        }

        u64 accP[8][4];
        u64 zero = pack2(0.f, 0.f);
#pragma unroll
        for (int p = 0; p < 8; p++)
#pragma unroll
            for (int c = 0; c < 4; c++) accP[p][c] = zero;

        for (int kc = 0; kc < 4; kc++) {
            int cur = kc & 1;
            __syncthreads();
            if (kc < 3) {
                prefetch(kc + 1, cur ^ 1);
                cp_wait1();
            } else {
                cp_wait0();
            }
            __syncthreads();

            const float* Wcur = cur ? Wsh1 : Wsh0;
#pragma unroll
            for (int kk = 0; kk < 16; kk++) {
                float4 w4 = *reinterpret_cast<const float4*>(&Wcur[kk * 256 + col]);
                u64 wd0 = pack2(w4.x, w4.x);
                u64 wd1 = pack2(w4.y, w4.y);
                u64 wd2 = pack2(w4.z, w4.z);
                u64 wd3 = pack2(w4.w, w4.w);
                const u64* hp = reinterpret_cast<const u64*>(
                    &hsh[(kc * 16 + kk) * HPAD + ty * 16]);
#pragma unroll
                for (int p = 0; p < 8; p++) {
                    u64 h2v = hp[p];
                    accP[p][0] = fma2(h2v, wd0, accP[p][0]);
                    accP[p][1] = fma2(h2v, wd1, accP[p][1]);
                    accP[p][2] = fma2(h2v, wd2, accP[p][2]);
                    accP[p][3] = fma2(h2v, wd3, accP[p][3]);
                }
            }
        }
        int half = col >> 7;
        int cc = col & 127;
        float* dst = half ? g_Zs : g_Zd;
#pragma unroll
        for (int p = 0; p < 8; p++) {
            float4 lo4, hi4;
            unpack2(accP[p][0], lo4.x, hi4.x);
            unpack2(accP[p][1], lo4.y, hi4.y);
            unpack2(accP[p][2], lo4.z, hi4.z);
            unpack2(accP[p][3], lo4.w, hi4.w);
            *reinterpret_cast<float4*>(&dst[(size_t)(r0 + ty * 16 + 2 * p) * FCO + cc]) = lo4;
            *reinterpret_cast<float4*>(&dst[(size_t)(r0 + ty * 16 + 2 * p + 1) * FCO + cc]) = hi4;
        }
    } else {
        // ================= table body (threads 0..127 active) =================
        float* v2   = smem_all;            // [BINS]
        float* p    = smem_all + 128;      // [BINS]
        float* q    = smem_all + 256;      // [AFL]
        float* redA = smem_all + 320;      // [4]
        float* redB = smem_all + 324;      // [4]
        int tb = blockIdx.x - NPROJ;
        float a = (float)tb / (float)(TBL - 1);
        bool act = tid < FCO;

        if (act && tid < BINS) {
            float v = fmaf(a, w1[tid], b1[tid]);
            v2[tid] = v > 0.f ? v : 0.01f * v;
        }
        __syncthreads();
        if (act) {
            float v3 = -3.0e38f;
            if (tid < BINS) {
                float acc = fmaf(alpha[0], v2[tid], b2[tid]);
#pragma unroll 4
                for (int k = 0; k < BINS; k++) acc = fmaf(v2[k], w2[k * BINS + tid], acc);
                v3 = acc;
            }
            float m = v3;
#pragma unroll
            for (int o = 16; o; o >>= 1) m = fmaxf(m, __shfl_xor_sync(0xffffffffu, m, o));
            if ((tid & 31) == 0) redA[tid >> 5] = m;
            // store v3 into p temporarily for phase 2
            p[tid] = v3;
        }
        __syncthreads();
        if (act) {
            float m = fmaxf(fmaxf(redA[0], redA[1]), fmaxf(redA[2], redA[3]));
            float v3 = p[tid];
            float ex = (tid < BINS) ? expf(v3 - m) : 0.f;
            float s = ex;
#pragma unroll
            for (int o = 16; o; o >>= 1) s += __shfl_xor_sync(0xffffffffu, s, o);
            if ((tid & 31) == 0) redB[tid >> 5] = s;
            // stash ex in v2's shadow: reuse p after sync
            q[0] = q[0];   // no-op
            p[tid] = ex;   // p now holds ex
        }
        __syncthreads();
        if (act) {
            float s = (redB[0] + redB[1]) + (redB[2] + redB[3]);
            float inv = 1.f / s;
            if (tid < BINS) p[tid] = p[tid] * inv;   // p = softmax
        }
        __syncthreads();
        if (act && tid < AFL) {
            float acc = 0.f;
#pragma unroll 4
            for (int j = 0; j < BINS; j++) acc = fmaf(p[j], lut[j * AFL + tid], acc);
            q[tid] = acc;
        }
        __syncthreads();
        if (act) {
            float acc = fcb[tid];
#pragma unroll 4
            for (int mm = 0; mm < AFL; mm++)
                acc = fmaf(q[mm], fcW[(2 * AFL + mm) * FCO + tid], acc);
            g_T[tb * FCO + tid] = acc;
        }
    }
}

// ---------------- pass C: flat edge-parallel BN1 stats ----------------
__global__ void __launch_bounds__(256) k_edgeC()
{
    __shared__ float sred[8 * 256];
    int tid = threadIdx.x;
    int warp = tid >> 5, lane = tid & 31;
    int gwarp = blockIdx.x * 8 + warp;
    int nwarp = gridDim.x * 8;
    const float4* T4  = reinterpret_cast<const float4*>(g_T);
    const float4* Zd4 = reinterpret_cast<const float4*>(g_Zd);
    const float4* Zs4 = reinterpret_cast<const float4*>(g_Zs);
    float4 ps = {0,0,0,0}, pq = {0,0,0,0};

    for (int e0 = gwarp * 4; e0 < N_EDGES; e0 += nwarp * 4) {
        int4   ss = __ldg(reinterpret_cast<const int4*>(g_psrc + e0));
        int4   dd = __ldg(reinterpret_cast<const int4*>(g_pdst + e0));
        float4 aa = __ldg(reinterpret_cast<const float4*>(g_pattr + e0));
        float4 zs0 = __ldg(Zs4 + (size_t)ss.x * 32 + lane);
        float4 zs1 = __ldg(Zs4 + (size_t)ss.y * 32 + lane);
        float4 zs2 = __ldg(Zs4 + (size_t)ss.z * 32 + lane);
        float4 zs3 = __ldg(Zs4 + (size_t)ss.w * 32 + lane);
        float4 zd0 = __ldg(Zd4 + (size_t)dd.x * 32 + lane);
        float4 zd1 = __ldg(Zd4 + (size_t)dd.y * 32 + lane);
        float4 zd2 = __ldg(Zd4 + (size_t)dd.z * 32 + lane);
        float4 zd3 = __ldg(Zd4 + (size_t)dd.w * 32 + lane);

#define DOEDGE_C(ZD, ZS, A)                                                  \
        {                                                                    \
            float pos = fminf(fmaxf((A) * (float)(TBL - 1), 0.f),            \
                              (float)(TBL - 1));                             \
            int t0 = min((int)pos, TBL - 2);                                 \
            float w = pos - (float)t0;                                       \
            float4 T0 = __ldg(T4 + t0 * 32 + lane);                          \
            float4 T1 = __ldg(T4 + (t0 + 1) * 32 + lane);                    \
            float zx = ZD.x + ZS.x + fmaf(w, T1.x - T0.x, T0.x);             \
            float zy = ZD.y + ZS.y + fmaf(w, T1.y - T0.y, T0.y);             \
            float zz = ZD.z + ZS.z + fmaf(w, T1.z - T0.z, T0.z);             \
            float zw = ZD.w + ZS.w + fmaf(w, T1.w - T0.w, T0.w);             \
            ps.x += zx; ps.y += zy; ps.z += zz; ps.w += zw;                  \
            pq.x = fmaf(zx, zx, pq.x); pq.y = fmaf(zy, zy, pq.y);            \
            pq.z = fmaf(zz, zz, pq.z); pq.w = fmaf(zw, zw, pq.w);            \
        }
        DOEDGE_C(zd0, zs0, aa.x)
        DOEDGE_C(zd1, zs1, aa.y)
        DOEDGE_C(zd2, zs2, aa.z)
        DOEDGE_C(zd3, zs3, aa.w)
#undef DOEDGE_C
    }
    {
        float* sb = &sred[warp * 256];
        int c4 = lane * 4;
        sb[c4 + 0] = ps.x; sb[c4 + 1] = ps.y; sb[c4 + 2] = ps.z; sb[c4 + 3] = ps.w;
        sb[128 + c4 + 0] = pq.x; sb[128 + c4 + 1] = pq.y;
        sb[128 + c4 + 2] = pq.z; sb[128 + c4 + 3] = pq.w;
    }
    __syncthreads();
    float v = 0.f;
#pragma unroll
    for (int w = 0; w < 8; w++) v += sred[w * 256 + tid];
    g_part1[blockIdx.x * 256 + tid] = v;
}

__global__ void __launch_bounds__(256) k_red1(
    const float* __restrict__ g1, const float* __restrict__ b1)
{
    __shared__ float ssum[256], ssq[256];
    int c = blockIdx.x;
    int t = threadIdx.x;
    float s = 0.f, q = 0.f;
    for (int r = t; r < EGRID; r += 256) {
        s += g_part1[r * 256 + c];
        q += g_part1[r * 256 + 128 + c];
    }
    ssum[t] = s; ssq[t] = q;
    __syncthreads();
    for (int o = 128; o; o >>= 1) {
        if (t < o) { ssum[t] += ssum[t + o]; ssq[t] += ssq[t + o]; }
        __syncthreads();
    }
    if (t == 0) {
        const float invE = 1.f / (float)N_EDGES;
        float mu = ssum[0] * invE;
        float var = ssq[0] * invE - mu * mu;
        float sc = rsqrtf(var + EPS_BN) * g1[c];
        g_bn1sc[c] = sc;
        g_bn1sh[c] = fmaf(-mu, sc, b1[c]);
    }
}

// ---------------- pass D: segment 4-wide (final form) ----------------
__global__ void __launch_bounds__(256) k_edgeD()
{
    __shared__ float sred[8 * 128];
    int tid = threadIdx.x;
    int warp = tid >> 5, lane = tid & 31;
    int cl = lane & 15, eh = lane >> 4;
    int gw = blockIdx.x * 8 + warp;
    int nw = gridDim.x * 8;
    const float4* T4 = reinterpret_cast<const float4*>(g_T);
    float4 sc0 = reinterpret_cast<const float4*>(g_bn1sc)[cl];
    float4 sc1 = reinterpret_cast<const float4*>(g_bn1sc)[16 + cl];
    float4 sh0 = reinterpret_cast<const float4*>(g_bn1sh)[cl];
    float4 sh1 = reinterpret_cast<const float4*>(g_bn1sh)[16 + cl];
    float4 ps = {0,0,0,0}, pq = {0,0,0,0};

    for (int n = gw; n < N_NODES; n += nw) {
        int beg = g_segstart[n], end = g_segstart[n + 1];
        float4 acc = {0,0,0,0};
        if (beg < end) {
            const float4* zdp = reinterpret_cast<const float4*>(&g_Zd[(size_t)n * FCO]);
            float4 zd0 = __ldg(zdp + cl), zd1 = __ldg(zdp + 16 + cl);

            auto doedge = [&](const float4& zs0, const float4& zs1, float a) {
                float pos = fminf(fmaxf(a * (float)(TBL - 1), 0.f), (float)(TBL - 1));
                int t0 = min((int)pos, TBL - 2);
                float w = pos - (float)t0;
                float4 T0l = __ldg(T4 + t0 * 32 + cl);
                float4 T0h = __ldg(T4 + t0 * 32 + 16 + cl);
                float4 T1l = __ldg(T4 + (t0 + 1) * 32 + cl);
                float4 T1h = __ldg(T4 + (t0 + 1) * 32 + 16 + cl);
                float4 z0, z1;
                z0.x = zd0.x + zs0.x + fmaf(w, T1l.x - T0l.x, T0l.x);
                z0.y = zd0.y + zs0.y + fmaf(w, T1l.y - T0l.y, T0l.y);
                z0.z = zd0.z + zs0.z + fmaf(w, T1l.z - T0l.z, T0l.z);
                z0.w = zd0.w + zs0.w + fmaf(w, T1l.w - T0l.w, T0l.w);
                z1.x = zd1.x + zs1.x + fmaf(w, T1h.x - T0h.x, T0h.x);
                z1.y = zd1.y + zs1.y + fmaf(w, T1h.y - T0h.y, T0h.y);
                z1.z = zd1.z + zs1.z + fmaf(w, T1h.z - T0h.z, T0h.z);
                z1.w = zd1.w + zs1.w + fmaf(w, T1h.w - T0h.w, T0h.w);
                float fx = fmaxf(fmaf(z0.x, sc0.x, sh0.x), 0.f);
                float fy = fmaxf(fmaf(z0.y, sc0.y, sh0.y), 0.f);
                float fz = fmaxf(fmaf(z0.z, sc0.z, sh0.z), 0.f);
                float fw = fmaxf(fmaf(z0.w, sc0.w, sh0.w), 0.f);
                float gx = fmaxf(fmaf(z1.x, sc1.x, sh1.x), 0.f);
                float gy = fmaxf(fmaf(z1.y, sc1.y, sh1.y), 0.f);
                float gz = fmaxf(fmaf(z1.z, sc1.z, sh1.z), 0.f);
                float gw2 = fmaxf(fmaf(z1.w, sc1.w, sh1.w), 0.f);
                acc.x = fmaf(fx, gx, acc.x);
                acc.y = fmaf(fy, gy, acc.y);
                acc.z = fmaf(fz, gz, acc.z);
                acc.w = fmaf(fw, gw2, acc.w);
            };

            for (int base = beg; base < end; base += 32) {
                int e = base + lane;
                int sv = 0; float av = 0.f;
                if (e < end) { sv = g_psrc[e]; av = g_pattr[e]; }
                int cnt = min(32, end - base);
                int j = 0;
                for (; j + 4 <= cnt; j += 4) {
                    int iA = j + eh, iB = j + 2 + eh;
                    int sA = __shfl_sync(0xffffffffu, sv, iA);
                    int sB = __shfl_sync(0xffffffffu, sv, iB);
                    float aA = __shfl_sync(0xffffffffu, av, iA);
                    float aB = __shfl_sync(0xffffffffu, av, iB);
                    const float4* zA = reinterpret_cast<const float4*>(&g_Zs[(size_t)sA * FCO]);
                    const float4* zB = reinterpret_cast<const float4*>(&g_Zs[(size_t)sB * FCO]);
                    float4 zA0 = __ldg(zA + cl), zA1 = __ldg(zA + 16 + cl);
                    float4 zB0 = __ldg(zB + cl), zB1 = __ldg(zB + 16 + cl);
                    doedge(zA0, zA1, aA);
                    doedge(zB0, zB1, aB);
                }
                for (; j + 2 <= cnt; j += 2) {
                    int iA = j + eh;
                    int sA = __shfl_sync(0xffffffffu, sv, iA);
                    float aA = __shfl_sync(0xffffffffu, av, iA);
                    const float4* zA = reinterpret_cast<const float4*>(&g_Zs[(size_t)sA * FCO]);
                    float4 zA0 = __ldg(zA + cl), zA1 = __ldg(zA + 16 + cl);
                    doedge(zA0, zA1, aA);
                }
                if (j < cnt) {
                    int sA = __shfl_sync(0xffffffffu, sv, j);
                    float aA = __shfl_sync(0xffffffffu, av, j);
                    if (eh == 0) {
                        const float4* zA = reinterpret_cast<const float4*>(&g_Zs[(size_t)sA * FCO]);
                        float4 zA0 = __ldg(zA + cl), zA1 = __ldg(zA + 16 + cl);
                        doedge(zA0, zA1, aA);
                    }
                }
            }
        }
        acc.x += __shfl_down_sync(0xffffffffu, acc.x, 16);
        acc.y += __shfl_down_sync(0xffffffffu, acc.y, 16);
        acc.z += __shfl_down_sync(0xffffffffu, acc.z, 16);
        acc.w += __shfl_down_sync(0xffffffffu, acc.w, 16);
        if (eh == 0) {
            reinterpret_cast<float4*>(&g_aggr[(size_t)n * AFL])[cl] = acc;
            ps.x += acc.x; ps.y += acc.y; ps.z += acc.z; ps.w += acc.w;
            pq.x = fmaf(acc.x, acc.x, pq.x); pq.y = fmaf(acc.y, acc.y, pq.y);
            pq.z = fmaf(acc.z, acc.z, pq.z); pq.w = fmaf(acc.w, acc.w, pq.w);
        }
    }
    if (eh == 0) {
        float* sb = &sred[warp * 128];
        int c4 = cl * 4;
        sb[c4 + 0] = ps.x; sb[c4 + 1] = ps.y; sb[c4 + 2] = ps.z; sb[c4 + 3] = ps.w;
        sb[64 + c4 + 0] = pq.x; sb[64 + c4 + 1] = pq.y; sb[64 + c4 + 2] = pq.z; sb[64 + c4 + 3] = pq.w;
    }
    __syncthreads();
    if (tid < 128) {
        float v = 0.f;
#pragma unroll
        for (int w = 0; w < 8; w++) v += sred[w * 128 + tid];
        g_part2[blockIdx.x * 128 + tid] = v;
    }
}

__global__ void __launch_bounds__(256) k_red2(
    const float* __restrict__ g2, const float* __restrict__ b2)
{
    __shared__ float ssum[256], ssq[256];
    int c = blockIdx.x;
    int t = threadIdx.x;
    float s = 0.f, q = 0.f;
    for (int r = t; r < DGRID; r += 256) {
        s += g_part2[r * 128 + c];
        q += g_part2[r * 128 + 64 + c];
    }
    ssum[t] = s; ssq[t] = q;
    __syncthreads();
    for (int o = 128; o; o >>= 1) {
        if (t < o) { ssum[t] += ssum[t + o]; ssq[t] += ssq[t + o]; }
        __syncthreads();
    }
    if (t == 0) {
        const float invN = 1.f / (float)N_NODES;
        float mu = ssum[0] * invN;
        float var = ssq[0] * invN - mu * mu;
        float sc = rsqrtf(var + EPS_BN) * g2[c];
        g_bn2sc[c] = sc;
        g_bn2sh[c] = fmaf(-mu, sc, b2[c]);
    }
}

// ---------------- launch ----------------
extern "C" void kernel_launch(void* const* d_in, const int* in_sizes, int n_in,
                              void* d_out, int out_size)
{
    const float* x     = (const float*)d_in[0];
    const int*   ei    = (const int*)  d_in[1];
    const float* ea    = (const float*)d_in[2];
    const int*   bs    = (const int*)  d_in[3];
    const float* att   = (const float*)d_in[4];
    const float* embW  = (const float*)d_in[5];
    const float* embb  = (const float*)d_in[6];
    const float* adw1  = (const float*)d_in[7];
    const float* adb1  = (const float*)d_in[8];
    const float* adw2  = (const float*)d_in[9];
    const float* adb2  = (const float*)d_in[10];
    const float* adal  = (const float*)d_in[11];
    const float* adlut = (const float*)d_in[12];
    const float* fcW   = (const float*)d_in[13];
    const float* fcb   = (const float*)d_in[14];
    const float* bn1g  = (const float*)d_in[15];
    const float* bn1b  = (const float*)d_in[16];
    const float* bn2g  = (const float*)d_in[17];
    const float* bn2b  = (const float*)d_in[18];
    const float* ppW   = (const float*)d_in[19];
    const float* ppb   = (const float*)d_in[20];
    float* out = (float*)d_out;

    k_hist<<<N_EDGES / 1024, 1024>>>(ei, out, out_size);
    k_scan<<<1, 1024>>>();
    k_scatter<<<N_EDGES / 1024, 1024>>>(ei, ea);
    k_embed_pool<<<N_NODES / PB, 256>>>(x, att, embW, embb, ppW, ppb, out, bs);

    for (int l = 0; l < NCONV; l++) {
        k_projtable<<<NPROJ + TBL, 256>>>(
            fcW + l * (3 * AFL) * FCO,
            adw1 + l * BINS, adb1 + l * BINS,
            adw2 + l * BINS * BINS, adb2 + l * BINS,
            adal + l, adlut + l * BINS * AFL,
            fcb + l * FCO);
        k_edgeC<<<EGRID, 256>>>();
        k_red1<<<FCO, 256>>>(bn1g + l * FCO, bn1b + l * FCO);
        k_edgeD<<<DGRID, 256>>>();
        k_red2<<<AFL, 256>>>(bn2g + l * AFL, bn2b + l * AFL);
        k_update_pool<<<N_NODES / PB, 256>>>(ppW, ppb, out, bs);
    }
}

// round 16
// speedup vs baseline: 1.1454x; 1.0168x over previous
#include <cuda_runtime.h>
#include <cuda_bf16.h>
#include <cstdint>

#define N_NODES 51200
#define N_EDGES 614400
#define ORIG    92
#define AFL     64
#define BINS    100
#define NCONV   3
#define TBL     128
#define FCO     128      // 2*AFL
#define EPS_BN  1e-5f
#define EGRID   1024
#define DGRID   2048
#define PROJ_ROWS 64
#define NPROJ   (N_NODES / PROJ_ROWS)     // 800
#define HPAD    68
#define PB      64
#define HT_PAD  68
#define KC      32

typedef unsigned long long u64;
__device__ __forceinline__ u64 pack2(float lo, float hi) {
    u64 r; asm("mov.b64 %0, {%1, %2};" : "=l"(r) : "f"(lo), "f"(hi)); return r;
}
__device__ __forceinline__ void unpack2(u64 v, float& lo, float& hi) {
    asm("mov.b64 {%0, %1}, %2;" : "=f"(lo), "=f"(hi) : "l"(v));
}
__device__ __forceinline__ u64 fma2(u64 a, u64 b, u64 c) {
    u64 d; asm("fma.rn.f32x2 %0, %1, %2, %3;" : "=l"(d) : "l"(a), "l"(b), "l"(c));
    return d;
}
__device__ __forceinline__ void cp_async16(uint32_t saddr, const void* gptr) {
    asm volatile("cp.async.cg.shared.global [%0], [%1], 16;"
                 :: "r"(saddr), "l"(gptr));
}
__device__ __forceinline__ void cp_commit() {
    asm volatile("cp.async.commit_group;" ::: "memory");
}
__device__ __forceinline__ void cp_wait1() {
    asm volatile("cp.async.wait_group 1;" ::: "memory");
}
__device__ __forceinline__ void cp_wait0() {
    asm volatile("cp.async.wait_group 0;" ::: "memory");
}

// ---------------- device scratch (static, no allocations) ----------------
__device__ float g_h[N_NODES * AFL];
__device__ float g_Zd[N_NODES * FCO];
__device__ float g_Zs[N_NODES * FCO];
__device__ float g_T[TBL * FCO];
__device__ float g_aggr[N_NODES * AFL];
__device__ float g_part1[EGRID * 256];
__device__ float g_part2[DGRID * 128];
__device__ float g_bn1sc[FCO], g_bn1sh[FCO];
__device__ float g_bn2sc[AFL], g_bn2sh[AFL];
__device__ int   g_cnt[N_NODES];              // zero-init; re-zeroed by k_scan
__device__ int   g_segstart[N_NODES + 1];
__device__ int   g_off[N_NODES];
__device__ int   g_psrc[N_EDGES];
__device__ int   g_pdst[N_EDGES];
__device__ float g_pattr[N_EDGES];

// ---------------- edge sort ----------------
__global__ void __launch_bounds__(1024) k_hist(const int* __restrict__ ei,
                                               float* __restrict__ out, int osz) {
    int e = blockIdx.x * blockDim.x + threadIdx.x;
    if (e < osz) out[e] = 0.f;
    if (e < N_EDGES) atomicAdd(&g_cnt[ei[N_EDGES + e]], 1);
}

__global__ void __launch_bounds__(1024) k_scan() {
    __shared__ int wsum[32];
    __shared__ int carry;
    int tid = threadIdx.x;
    int lane = tid & 31, wid = tid >> 5;
    if (tid == 0) carry = 0;
    __syncthreads();
    for (int base = 0; base < N_NODES; base += 1024) {
        int v = g_cnt[base + tid];
        g_cnt[base + tid] = 0;
        int x = v;
#pragma unroll
        for (int o = 1; o < 32; o <<= 1) {
            int t = __shfl_up_sync(0xffffffffu, x, o);
            if (lane >= o) x += t;
        }
        if (lane == 31) wsum[wid] = x;
        __syncthreads();
        if (wid == 0) {
            int sv = wsum[lane];
#pragma unroll
            for (int o = 1; o < 32; o <<= 1) {
                int t = __shfl_up_sync(0xffffffffu, sv, o);
                if (lane >= o) sv += t;
            }
            wsum[lane] = sv;
        }
        __syncthreads();
        int woff = (wid > 0) ? wsum[wid - 1] : 0;
        int ex = carry + woff + x - v;
        g_segstart[base + tid] = ex;
        g_off[base + tid] = ex;
        __syncthreads();
        if (tid == 0) carry += wsum[31];
        __syncthreads();
    }
    if (tid == 0) g_segstart[N_NODES] = N_EDGES;
}

__global__ void __launch_bounds__(1024) k_scatter(const int* __restrict__ ei,
                                                  const float* __restrict__ ea) {
    int e = blockIdx.x * blockDim.x + threadIdx.x;
    if (e < N_EDGES) {
        int dst = ei[N_EDGES + e];
        int pos = atomicAdd(&g_off[dst], 1);
        g_psrc[pos] = ei[e];
        g_pdst[pos] = dst;
        g_pattr[pos] = ea[e];
    }
}

// ---------------- shared pool helper (scalar R11 form) ----------------
__device__ __forceinline__ void pool_tile(
    const float* __restrict__ ppWs, const float* __restrict__ hsT,
    float* __restrict__ red, const float* __restrict__ ppb,
    float* __restrict__ out, int n0, int numAtom, int tx, int ty, int tid)
{
    const float4* W4 = reinterpret_cast<const float4*>(ppWs);
    const float4* H4 = reinterpret_cast<const float4*>(hsT);
    float4 pb = *reinterpret_cast<const float4*>(ppb + 4 * tx);
    float4 p0 = pb, p1 = pb, p2 = pb, p3 = pb;
#pragma unroll 8
    for (int k = 0; k < AFL; k++) {
        float4 w4 = W4[k * 16 + tx];
        float4 h4 = H4[k * (HT_PAD / 4) + ty];
        p0.x = fmaf(h4.x, w4.x, p0.x); p0.y = fmaf(h4.x, w4.y, p0.y);
        p0.z = fmaf(h4.x, w4.z, p0.z); p0.w = fmaf(h4.x, w4.w, p0.w);
        p1.x = fmaf(h4.y, w4.x, p1.x); p1.y = fmaf(h4.y, w4.y, p1.y);
        p1.z = fmaf(h4.y, w4.z, p1.z); p1.w = fmaf(h4.y, w4.w, p1.w);
        p2.x = fmaf(h4.z, w4.x, p2.x); p2.y = fmaf(h4.z, w4.y, p2.y);
        p2.z = fmaf(h4.z, w4.z, p2.z); p2.w = fmaf(h4.z, w4.w, p2.w);
        p3.x = fmaf(h4.w, w4.x, p3.x); p3.y = fmaf(h4.w, w4.y, p3.y);
        p3.z = fmaf(h4.w, w4.z, p3.z); p3.w = fmaf(h4.w, w4.w, p3.w);
    }
    float4 pv[4] = {p0, p1, p2, p3};
    float4 val[4];
#pragma unroll
    for (int i = 0; i < 4; i++) {
        float4 p = pv[i];
        float m = fmaxf(fmaxf(p.x, p.y), fmaxf(p.z, p.w));
#pragma unroll
        for (int o = 1; o < 16; o <<= 1)
            m = fmaxf(m, __shfl_xor_sync(0xffffffffu, m, o));
        float4 e;
        e.x = expf(p.x - m); e.y = expf(p.y - m);
        e.z = expf(p.z - m); e.w = expf(p.w - m);
        float s = (e.x + e.y) + (e.z + e.w);
#pragma unroll
        for (int o = 1; o < 16; o <<= 1)
            s += __shfl_xor_sync(0xffffffffu, s, o);
        float inv = 1.f / s;
        val[i] = make_float4(e.x * inv, e.y * inv, e.z * inv, e.w * inv);
    }
    bool same = (n0 / numAtom) == ((n0 + PB - 1) / numAtom);
    if (same) {
        float4 cs;
        cs.x = (val[0].x + val[1].x) + (val[2].x + val[3].x);
        cs.y = (val[0].y + val[1].y) + (val[2].y + val[3].y);
        cs.z = (val[0].z + val[1].z) + (val[2].z + val[3].z);
        cs.w = (val[0].w + val[1].w) + (val[2].w + val[3].w);
        *reinterpret_cast<float4*>(&red[ty * 64 + 4 * tx]) = cs;
        __syncthreads();
        if (tid < 64) {
            float s = 0.f;
#pragma unroll
            for (int r = 0; r < 16; r++) s += red[r * 64 + tid];
            atomicAdd(&out[(n0 / numAtom) * AFL + tid], s);
        }
    } else {
#pragma unroll
        for (int i = 0; i < 4; i++) {
            int node = n0 + 4 * ty + i;
            int cry = node / numAtom;
            atomicAdd(&out[cry * AFL + 4 * tx + 0], val[i].x);
            atomicAdd(&out[cry * AFL + 4 * tx + 1], val[i].y);
            atomicAdd(&out[cry * AFL + 4 * tx + 2], val[i].z);
            atomicAdd(&out[cry * AFL + 4 * tx + 3], val[i].w);
        }
    }
}

// ---------------- embedding + initial pooling ----------------
__global__ void __launch_bounds__(256) k_embed_pool(
    const float* __restrict__ x, const float* __restrict__ att,
    const float* __restrict__ W, const float* __restrict__ b,
    const float* __restrict__ ppW, const float* __restrict__ ppb,
    float* __restrict__ out, const int* __restrict__ bs)
{
    __shared__ float sbuf[KC * AFL + KC * HT_PAD];
    __shared__ float hsT[AFL * HT_PAD];
    __shared__ float red[16 * AFL];
    float* Wc = sbuf;
    float* xsT = sbuf + KC * AFL;
    int tid = threadIdx.x;
    int tx = tid & 15, ty = tid >> 4;
    int n0 = blockIdx.x * PB;

    float4 b4 = *reinterpret_cast<const float4*>(b + 4 * tx);
    float4 a0 = b4, a1 = b4, a2 = b4, a3 = b4;

    for (int kc = 0; kc < ORIG; kc += KC) {
        int kl = min(KC, ORIG - kc);
        __syncthreads();
        for (int i = tid; i < kl * AFL; i += 256) Wc[i] = W[kc * AFL + i];
        for (int idx = tid; idx < PB * KC; idx += 256) {
            int n = idx >> 5, k = idx & 31;
            if (k < kl)
                xsT[k * HT_PAD + n] = x[(size_t)(n0 + n) * ORIG + kc + k] * att[kc + k];
        }
        __syncthreads();
        const float4* Wc4 = reinterpret_cast<const float4*>(Wc);
        const float4* X4 = reinterpret_cast<const float4*>(xsT);
#pragma unroll 4
        for (int k = 0; k < kl; k++) {
            float4 w4 = Wc4[k * 16 + tx];
            float4 h4 = X4[k * (HT_PAD / 4) + ty];
            a0.x = fmaf(h4.x, w4.x, a0.x); a0.y = fmaf(h4.x, w4.y, a0.y);
            a0.z = fmaf(h4.x, w4.z, a0.z); a0.w = fmaf(h4.x, w4.w, a0.w);
            a1.x = fmaf(h4.y, w4.x, a1.x); a1.y = fmaf(h4.y, w4.y, a1.y);
            a1.z = fmaf(h4.y, w4.z, a1.z); a1.w = fmaf(h4.y, w4.w, a1.w);
            a2.x = fmaf(h4.z, w4.x, a2.x); a2.y = fmaf(h4.z, w4.y, a2.y);
            a2.z = fmaf(h4.z, w4.z, a2.z); a2.w = fmaf(h4.z, w4.w, a2.w);
            a3.x = fmaf(h4.w, w4.x, a3.x); a3.y = fmaf(h4.w, w4.y, a3.y);
            a3.z = fmaf(h4.w, w4.z, a3.z); a3.w = fmaf(h4.w, w4.w, a3.w);
        }
    }
    float4 av[4] = {a0, a1, a2, a3};
#pragma unroll
    for (int i = 0; i < 4; i++) {
        int node = n0 + 4 * ty + i;
        *reinterpret_cast<float4*>(&g_h[(size_t)node * AFL + 4 * tx]) = av[i];
        hsT[(4 * tx + 0) * HT_PAD + 4 * ty + i] = av[i].x;
        hsT[(4 * tx + 1) * HT_PAD + 4 * ty + i] = av[i].y;
        hsT[(4 * tx + 2) * HT_PAD + 4 * ty + i] = av[i].z;
        hsT[(4 * tx + 3) * HT_PAD + 4 * ty + i] = av[i].w;
    }
    __syncthreads();
    for (int i = tid; i < AFL * AFL; i += 256) sbuf[i] = ppW[i];
    __syncthreads();
    int numAtom = N_NODES / bs[0];
    pool_tile(sbuf, hsT, red, ppb, out, n0, numAtom, tx, ty, tid);
}

// ---------------- update + pooling ----------------
__global__ void __launch_bounds__(256) k_update_pool(
    const float* __restrict__ ppW, const float* __restrict__ ppb,
    float* __restrict__ out, const int* __restrict__ bs)
{
    __shared__ float ppWs[AFL * AFL];
    __shared__ float hsT[AFL * HT_PAD];
    __shared__ float red[16 * AFL];
    int tid = threadIdx.x;
    int tx = tid & 15, ty = tid >> 4;
    int n0 = blockIdx.x * PB;

    for (int i = tid; i < AFL * AFL; i += 256) ppWs[i] = ppW[i];
    for (int idx = tid; idx < PB * 16; idx += 256) {
        int n = idx >> 4, c4 = idx & 15;
        size_t base = (size_t)(n0 + n) * AFL + 4 * c4;
        float4 h4 = *reinterpret_cast<const float4*>(&g_h[base]);
        float4 g4 = *reinterpret_cast<const float4*>(&g_aggr[base]);
        float4 sc = reinterpret_cast<const float4*>(g_bn2sc)[c4];
        float4 sh = reinterpret_cast<const float4*>(g_bn2sh)[c4];
        float4 up;
        up.x = fmaxf(h4.x + fmaf(g4.x, sc.x, sh.x), 0.f);
        up.y = fmaxf(h4.y + fmaf(g4.y, sc.y, sh.y), 0.f);
        up.z = fmaxf(h4.z + fmaf(g4.z, sc.z, sh.z), 0.f);
        up.w = fmaxf(h4.w + fmaf(g4.w, sc.w, sh.w), 0.f);
        *reinterpret_cast<float4*>(&g_h[base]) = up;
        hsT[(4 * c4 + 0) * HT_PAD + n] = up.x;
        hsT[(4 * c4 + 1) * HT_PAD + n] = up.y;
        hsT[(4 * c4 + 2) * HT_PAD + n] = up.z;
        hsT[(4 * c4 + 3) * HT_PAD + n] = up.w;
    }
    __syncthreads();
    int numAtom = N_NODES / bs[0];
    pool_tile(ppWs, hsT, red, ppb, out, n0, numAtom, tx, ty, tid);
}

// ---------------- combined: proj (blocks < NPROJ) + table (blocks >= NPROJ) ----------------
__global__ void __launch_bounds__(256) k_projtable(
    const float* __restrict__ fcW,
    const float* __restrict__ w1, const float* __restrict__ b1,
    const float* __restrict__ w2, const float* __restrict__ b2,
    const float* __restrict__ alpha, const float* __restrict__ lut,
    const float* __restrict__ fcb)
{
    __shared__ float smem_all[2 * 16 * 256 + AFL * HPAD];
    int tid = threadIdx.x;

    if (blockIdx.x < NPROJ) {
        float* Wsh0 = smem_all;
        float* Wsh1 = smem_all + 16 * 256;
        float* hsh  = smem_all + 2 * 16 * 256;
        int tx = tid & 63;
        int ty = tid >> 6;
        int r0 = blockIdx.x * PROJ_ROWS;
        int col = 4 * tx;

        uint32_t wbase[2];
        wbase[0] = (uint32_t)__cvta_generic_to_shared(Wsh0);
        wbase[1] = (uint32_t)__cvta_generic_to_shared(Wsh1);

        auto prefetch = [&](int kc, int buf) {
#pragma unroll
            for (int q = 0; q < 4; q++) {
                int f = tid + q * 256;
                int kk = f >> 6;
                int c4 = f & 63;
                int h2 = c4 >> 5;
                int c2 = (c4 & 31) * 4;
                const float* g = &fcW[(size_t)(h2 * AFL + kc * 16 + kk) * FCO + c2];
                cp_async16(wbase[buf] + (uint32_t)f * 16u, g);
            }
            cp_commit();
        };

        prefetch(0, 0);

        for (int i = tid; i < PROJ_ROWS * AFL; i += 256) {
            int r = i >> 6, k = i & 63;
            hsh[k * HPAD + r] = g_h[(size_t)(r0 + r) * AFL + k];
        }

        u64 accP[8][4];
        u64 zero = pack2(0.f, 0.f);
#pragma unroll
        for (int p = 0; p < 8; p++)
#pragma unroll
            for (int c = 0; c < 4; c++) accP[p][c] = zero;

        for (int kc = 0; kc < 4; kc++) {
            int cur = kc & 1;
            __syncthreads();
            if (kc < 3) {
                prefetch(kc + 1, cur ^ 1);
                cp_wait1();
            } else {
                cp_wait0();
            }
            __syncthreads();

            const float* Wcur = cur ? Wsh1 : Wsh0;
#pragma unroll
            for (int kk = 0; kk < 16; kk++) {
                float4 w4 = *reinterpret_cast<const float4*>(&Wcur[kk * 256 + col]);
                u64 wd0 = pack2(w4.x, w4.x);
                u64 wd1 = pack2(w4.y, w4.y);
                u64 wd2 = pack2(w4.z, w4.z);
                u64 wd3 = pack2(w4.w, w4.w);
                const u64* hp = reinterpret_cast<const u64*>(
                    &hsh[(kc * 16 + kk) * HPAD + ty * 16]);
#pragma unroll
                for (int p = 0; p < 8; p++) {
                    u64 h2v = hp[p];
                    accP[p][0] = fma2(h2v, wd0, accP[p][0]);
                    accP[p][1] = fma2(h2v, wd1, accP[p][1]);
                    accP[p][2] = fma2(h2v, wd2, accP[p][2]);
                    accP[p][3] = fma2(h2v, wd3, accP[p][3]);
                }
            }
        }
        int half = col >> 7;
        int cc = col & 127;
        float* dst = half ? g_Zs : g_Zd;
#pragma unroll
        for (int p = 0; p < 8; p++) {
            float4 lo4, hi4;
            unpack2(accP[p][0], lo4.x, hi4.x);
            unpack2(accP[p][1], lo4.y, hi4.y);
            unpack2(accP[p][2], lo4.z, hi4.z);
            unpack2(accP[p][3], lo4.w, hi4.w);
            *reinterpret_cast<float4*>(&dst[(size_t)(r0 + ty * 16 + 2 * p) * FCO + cc]) = lo4;
            *reinterpret_cast<float4*>(&dst[(size_t)(r0 + ty * 16 + 2 * p + 1) * FCO + cc]) = hi4;
        }
    } else {
        float* v2   = smem_all;
        float* p    = smem_all + 128;
        float* q    = smem_all + 256;
        float* redA = smem_all + 320;
        float* redB = smem_all + 324;
        int tb = blockIdx.x - NPROJ;
        float a = (float)tb / (float)(TBL - 1);
        bool act = tid < FCO;

        if (act && tid < BINS) {
            float v = fmaf(a, w1[tid], b1[tid]);
            v2[tid] = v > 0.f ? v : 0.01f * v;
        }
        __syncthreads();
        if (act) {
            float v3 = -3.0e38f;
            if (tid < BINS) {
                float acc = fmaf(alpha[0], v2[tid], b2[tid]);
#pragma unroll 4
                for (int k = 0; k < BINS; k++) acc = fmaf(v2[k], w2[k * BINS + tid], acc);
                v3 = acc;
            }
            float m = v3;
#pragma unroll
            for (int o = 16; o; o >>= 1) m = fmaxf(m, __shfl_xor_sync(0xffffffffu, m, o));
            if ((tid & 31) == 0) redA[tid >> 5] = m;
            p[tid] = v3;
        }
        __syncthreads();
        if (act) {
            float m = fmaxf(fmaxf(redA[0], redA[1]), fmaxf(redA[2], redA[3]));
            float v3 = p[tid];
            float ex = (tid < BINS) ? expf(v3 - m) : 0.f;
            float s = ex;
#pragma unroll
            for (int o = 16; o; o >>= 1) s += __shfl_xor_sync(0xffffffffu, s, o);
            if ((tid & 31) == 0) redB[tid >> 5] = s;
            p[tid] = ex;
        }
        __syncthreads();
        if (act) {
            float s = (redB[0] + redB[1]) + (redB[2] + redB[3]);
            float inv = 1.f / s;
            if (tid < BINS) p[tid] = p[tid] * inv;
        }
        __syncthreads();
        if (act && tid < AFL) {
            float acc = 0.f;
#pragma unroll 4
            for (int j = 0; j < BINS; j++) acc = fmaf(p[j], lut[j * AFL + tid], acc);
            q[tid] = acc;
        }
        __syncthreads();
        if (act) {
            float acc = fcb[tid];
#pragma unroll 4
            for (int mm = 0; mm < AFL; mm++)
                acc = fmaf(q[mm], fcW[(2 * AFL + mm) * FCO + tid], acc);
            g_T[tb * FCO + tid] = acc;
        }
    }
}

// ---------------- pass C: flat edge-parallel BN1 stats ----------------
__global__ void __launch_bounds__(256) k_edgeC()
{
    __shared__ float sred[8 * 256];
    int tid = threadIdx.x;
    int warp = tid >> 5, lane = tid & 31;
    int gwarp = blockIdx.x * 8 + warp;
    int nwarp = gridDim.x * 8;
    const float4* T4  = reinterpret_cast<const float4*>(g_T);
    const float4* Zd4 = reinterpret_cast<const float4*>(g_Zd);
    const float4* Zs4 = reinterpret_cast<const float4*>(g_Zs);
    float4 ps = {0,0,0,0}, pq = {0,0,0,0};

    for (int e0 = gwarp * 4; e0 < N_EDGES; e0 += nwarp * 4) {
        int4   ss = __ldg(reinterpret_cast<const int4*>(g_psrc + e0));
        int4   dd = __ldg(reinterpret_cast<const int4*>(g_pdst + e0));
        float4 aa = __ldg(reinterpret_cast<const float4*>(g_pattr + e0));
        float4 zs0 = __ldg(Zs4 + (size_t)ss.x * 32 + lane);
        float4 zs1 = __ldg(Zs4 + (size_t)ss.y * 32 + lane);
        float4 zs2 = __ldg(Zs4 + (size_t)ss.z * 32 + lane);
        float4 zs3 = __ldg(Zs4 + (size_t)ss.w * 32 + lane);
        float4 zd0 = __ldg(Zd4 + (size_t)dd.x * 32 + lane);
        float4 zd1 = __ldg(Zd4 + (size_t)dd.y * 32 + lane);
        float4 zd2 = __ldg(Zd4 + (size_t)dd.z * 32 + lane);
        float4 zd3 = __ldg(Zd4 + (size_t)dd.w * 32 + lane);

#define DOEDGE_C(ZD, ZS, A)                                                  \
        {                                                                    \
            float pos = fminf(fmaxf((A) * (float)(TBL - 1), 0.f),            \
                              (float)(TBL - 1));                             \
            int t0 = min((int)pos, TBL - 2);                                 \
            float w = pos - (float)t0;                                       \
            float4 T0 = __ldg(T4 + t0 * 32 + lane);                          \
            float4 T1 = __ldg(T4 + (t0 + 1) * 32 + lane);                    \
            float zx = ZD.x + ZS.x + fmaf(w, T1.x - T0.x, T0.x);             \
            float zy = ZD.y + ZS.y + fmaf(w, T1.y - T0.y, T0.y);             \
            float zz = ZD.z + ZS.z + fmaf(w, T1.z - T0.z, T0.z);             \
            float zw = ZD.w + ZS.w + fmaf(w, T1.w - T0.w, T0.w);             \
            ps.x += zx; ps.y += zy; ps.z += zz; ps.w += zw;                  \
            pq.x = fmaf(zx, zx, pq.x); pq.y = fmaf(zy, zy, pq.y);            \
            pq.z = fmaf(zz, zz, pq.z); pq.w = fmaf(zw, zw, pq.w);            \
        }
        DOEDGE_C(zd0, zs0, aa.x)
        DOEDGE_C(zd1, zs1, aa.y)
        DOEDGE_C(zd2, zs2, aa.z)
        DOEDGE_C(zd3, zs3, aa.w)
#undef DOEDGE_C
    }
    {
        float* sb = &sred[warp * 256];
        int c4 = lane * 4;
        sb[c4 + 0] = ps.x; sb[c4 + 1] = ps.y; sb[c4 + 2] = ps.z; sb[c4 + 3] = ps.w;
        sb[128 + c4 + 0] = pq.x; sb[128 + c4 + 1] = pq.y;
        sb[128 + c4 + 2] = pq.z; sb[128 + c4 + 3] = pq.w;
    }
    __syncthreads();
    float v = 0.f;
#pragma unroll
    for (int w = 0; w < 8; w++) v += sred[w * 256 + tid];
    g_part1[blockIdx.x * 256 + tid] = v;
}

__global__ void __launch_bounds__(256) k_red1(
    const float* __restrict__ g1, const float* __restrict__ b1)
{
    __shared__ float ssum[256], ssq[256];
    int c = blockIdx.x;
    int t = threadIdx.x;
    float s = 0.f, q = 0.f;
    for (int r = t; r < EGRID; r += 256) {
        s += g_part1[r * 256 + c];
        q += g_part1[r * 256 + 128 + c];
    }
    ssum[t] = s; ssq[t] = q;
    __syncthreads();
    for (int o = 128; o; o >>= 1) {
        if (t < o) { ssum[t] += ssum[t + o]; ssq[t] += ssq[t + o]; }
        __syncthreads();
    }
    if (t == 0) {
        const float invE = 1.f / (float)N_EDGES;
        float mu = ssum[0] * invE;
        float var = ssq[0] * invE - mu * mu;
        float sc = rsqrtf(var + EPS_BN) * g1[c];
        g_bn1sc[c] = sc;
        g_bn1sh[c] = fmaf(-mu, sc, b1[c]);
    }
}

// ---------------- pass D: segment 4-wide, higher occupancy ----------------
__global__ void __launch_bounds__(256, 3) k_edgeD()
{
    __shared__ float sred[8 * 128];
    int tid = threadIdx.x;
    int warp = tid >> 5, lane = tid & 31;
    int cl = lane & 15, eh = lane >> 4;
    int gw = blockIdx.x * 8 + warp;
    int nw = gridDim.x * 8;
    const float4* T4 = reinterpret_cast<const float4*>(g_T);
    float4 sc0 = reinterpret_cast<const float4*>(g_bn1sc)[cl];
    float4 sc1 = reinterpret_cast<const float4*>(g_bn1sc)[16 + cl];
    float4 sh0 = reinterpret_cast<const float4*>(g_bn1sh)[cl];
    float4 sh1 = reinterpret_cast<const float4*>(g_bn1sh)[16 + cl];
    float4 ps = {0,0,0,0}, pq = {0,0,0,0};

    for (int n = gw; n < N_NODES; n += nw) {
        int beg = g_segstart[n], end = g_segstart[n + 1];
        float4 acc = {0,0,0,0};
        if (beg < end) {
            const float4* zdp = reinterpret_cast<const float4*>(&g_Zd[(size_t)n * FCO]);
            float4 zd0 = __ldg(zdp + cl), zd1 = __ldg(zdp + 16 + cl);

            auto doedge = [&](const float4& zs0, const float4& zs1, float a) {
                float pos = fminf(fmaxf(a * (float)(TBL - 1), 0.f), (float)(TBL - 1));
                int t0 = min((int)pos, TBL - 2);
                float w = pos - (float)t0;
                float4 T0l = __ldg(T4 + t0 * 32 + cl);
                float4 T0h = __ldg(T4 + t0 * 32 + 16 + cl);
                float4 T1l = __ldg(T4 + (t0 + 1) * 32 + cl);
                float4 T1h = __ldg(T4 + (t0 + 1) * 32 + 16 + cl);
                float4 z0, z1;
                z0.x = zd0.x + zs0.x + fmaf(w, T1l.x - T0l.x, T0l.x);
                z0.y = zd0.y + zs0.y + fmaf(w, T1l.y - T0l.y, T0l.y);
                z0.z = zd0.z + zs0.z + fmaf(w, T1l.z - T0l.z, T0l.z);
                z0.w = zd0.w + zs0.w + fmaf(w, T1l.w - T0l.w, T0l.w);
                z1.x = zd1.x + zs1.x + fmaf(w, T1h.x - T0h.x, T0h.x);
                z1.y = zd1.y + zs1.y + fmaf(w, T1h.y - T0h.y, T0h.y);
                z1.z = zd1.z + zs1.z + fmaf(w, T1h.z - T0h.z, T0h.z);
                z1.w = zd1.w + zs1.w + fmaf(w, T1h.w - T0h.w, T0h.w);
                float fx = fmaxf(fmaf(z0.x, sc0.x, sh0.x), 0.f);
                float fy = fmaxf(fmaf(z0.y, sc0.y, sh0.y), 0.f);
                float fz = fmaxf(fmaf(z0.z, sc0.z, sh0.z), 0.f);
                float fw = fmaxf(fmaf(z0.w, sc0.w, sh0.w), 0.f);
                float gx = fmaxf(fmaf(z1.x, sc1.x, sh1.x), 0.f);
                float gy = fmaxf(fmaf(z1.y, sc1.y, sh1.y), 0.f);
                float gz = fmaxf(fmaf(z1.z, sc1.z, sh1.z), 0.f);
                float gw2 = fmaxf(fmaf(z1.w, sc1.w, sh1.w), 0.f);
                acc.x = fmaf(fx, gx, acc.x);
                acc.y = fmaf(fy, gy, acc.y);
                acc.z = fmaf(fz, gz, acc.z);
                acc.w = fmaf(fw, gw2, acc.w);
            };

            for (int base = beg; base < end; base += 32) {
                int e = base + lane;
                int sv = 0; float av = 0.f;
                if (e < end) { sv = g_psrc[e]; av = g_pattr[e]; }
                int cnt = min(32, end - base);
                int j = 0;
                for (; j + 4 <= cnt; j += 4) {
                    int iA = j + eh, iB = j + 2 + eh;
                    int sA = __shfl_sync(0xffffffffu, sv, iA);
                    int sB = __shfl_sync(0xffffffffu, sv, iB);
                    float aA = __shfl_sync(0xffffffffu, av, iA);
                    float aB = __shfl_sync(0xffffffffu, av, iB);
                    const float4* zA = reinterpret_cast<const float4*>(&g_Zs[(size_t)sA * FCO]);
                    const float4* zB = reinterpret_cast<const float4*>(&g_Zs[(size_t)sB * FCO]);
                    float4 zA0 = __ldg(zA + cl), zA1 = __ldg(zA + 16 + cl);
                    float4 zB0 = __ldg(zB + cl), zB1 = __ldg(zB + 16 + cl);
                    doedge(zA0, zA1, aA);
                    doedge(zB0, zB1, aB);
                }
                for (; j + 2 <= cnt; j += 2) {
                    int iA = j + eh;
                    int sA = __shfl_sync(0xffffffffu, sv, iA);
                    float aA = __shfl_sync(0xffffffffu, av, iA);
                    const float4* zA = reinterpret_cast<const float4*>(&g_Zs[(size_t)sA * FCO]);
                    float4 zA0 = __ldg(zA + cl), zA1 = __ldg(zA + 16 + cl);
                    doedge(zA0, zA1, aA);
                }
                if (j < cnt) {
                    int sA = __shfl_sync(0xffffffffu, sv, j);
                    float aA = __shfl_sync(0xffffffffu, av, j);
                    if (eh == 0) {
                        const float4* zA = reinterpret_cast<const float4*>(&g_Zs[(size_t)sA * FCO]);
                        float4 zA0 = __ldg(zA + cl), zA1 = __ldg(zA + 16 + cl);
                        doedge(zA0, zA1, aA);
                    }
                }
            }
        }
        acc.x += __shfl_down_sync(0xffffffffu, acc.x, 16);
        acc.y += __shfl_down_sync(0xffffffffu, acc.y, 16);
        acc.z += __shfl_down_sync(0xffffffffu, acc.z, 16);
        acc.w += __shfl_down_sync(0xffffffffu, acc.w, 16);
        if (eh == 0) {
            reinterpret_cast<float4*>(&g_aggr[(size_t)n * AFL])[cl] = acc;
            ps.x += acc.x; ps.y += acc.y; ps.z += acc.z; ps.w += acc.w;
            pq.x = fmaf(acc.x, acc.x, pq.x); pq.y = fmaf(acc.y, acc.y, pq.y);
            pq.z = fmaf(acc.z, acc.z, pq.z); pq.w = fmaf(acc.w, acc.w, pq.w);
        }
    }
    if (eh == 0) {
        float* sb = &sred[warp * 128];
        int c4 = cl * 4;
        sb[c4 + 0] = ps.x; sb[c4 + 1] = ps.y; sb[c4 + 2] = ps.z; sb[c4 + 3] = ps.w;
        sb[64 + c4 + 0] = pq.x; sb[64 + c4 + 1] = pq.y; sb[64 + c4 + 2] = pq.z; sb[64 + c4 + 3] = pq.w;
    }
    __syncthreads();
    if (tid < 128) {
        float v = 0.f;
#pragma unroll
        for (int w = 0; w < 8; w++) v += sred[w * 128 + tid];
        g_part2[blockIdx.x * 128 + tid] = v;
    }
}

__global__ void __launch_bounds__(256) k_red2(
    const float* __restrict__ g2, const float* __restrict__ b2)
{
    __shared__ float ssum[256], ssq[256];
    int c = blockIdx.x;
    int t = threadIdx.x;
    float s = 0.f, q = 0.f;
    for (int r = t; r < DGRID; r += 256) {
        s += g_part2[r * 128 + c];
        q += g_part2[r * 128 + 64 + c];
    }
    ssum[t] = s; ssq[t] = q;
    __syncthreads();
    for (int o = 128; o; o >>= 1) {
        if (t < o) { ssum[t] += ssum[t + o]; ssq[t] += ssq[t + o]; }
        __syncthreads();
    }
    if (t == 0) {
        const float invN = 1.f / (float)N_NODES;
        float mu = ssum[0] * invN;
        float var = ssq[0] * invN - mu * mu;
        float sc = rsqrtf(var + EPS_BN) * g2[c];
        g_bn2sc[c] = sc;
        g_bn2sh[c] = fmaf(-mu, sc, b2[c]);
    }
}

// ---------------- launch ----------------
extern "C" void kernel_launch(void* const* d_in, const int* in_sizes, int n_in,
                              void* d_out, int out_size)
{
    const float* x     = (const float*)d_in[0];
    const int*   ei    = (const int*)  d_in[1];
    const float* ea    = (const float*)d_in[2];
    const int*   bs    = (const int*)  d_in[3];
    const float* att   = (const float*)d_in[4];
    const float* embW  = (const float*)d_in[5];
    const float* embb  = (const float*)d_in[6];
    const float* adw1  = (const float*)d_in[7];
    const float* adb1  = (const float*)d_in[8];
    const float* adw2  = (const float*)d_in[9];
    const float* adb2  = (const float*)d_in[10];
    const float* adal  = (const float*)d_in[11];
    const float* adlut = (const float*)d_in[12];
    const float* fcW   = (const float*)d_in[13];
    const float* fcb   = (const float*)d_in[14];
    const float* bn1g  = (const float*)d_in[15];
    const float* bn1b  = (const float*)d_in[16];
    const float* bn2g  = (const float*)d_in[17];
    const float* bn2b  = (const float*)d_in[18];
    const float* ppW   = (const float*)d_in[19];
    const float* ppb   = (const float*)d_in[20];
    float* out = (float*)d_out;

    k_hist<<<N_EDGES / 1024, 1024>>>(ei, out, out_size);
    k_scan<<<1, 1024>>>();
    k_scatter<<<N_EDGES / 1024, 1024>>>(ei, ea);
    k_embed_pool<<<N_NODES / PB, 256>>>(x, att, embW, embb, ppW, ppb, out, bs);

    for (int l = 0; l < NCONV; l++) {
        k_projtable<<<NPROJ + TBL, 256>>>(
            fcW + l * (3 * AFL) * FCO,
            adw1 + l * BINS, adb1 + l * BINS,
            adw2 + l * BINS * BINS, adb2 + l * BINS,
            adal + l, adlut + l * BINS * AFL,
            fcb + l * FCO);
        k_edgeC<<<EGRID, 256>>>();
        k_red1<<<FCO, 256>>>(bn1g + l * FCO, bn1b + l * FCO);
        k_edgeD<<<DGRID, 256>>>();
        k_red2<<<AFL, 256>>>(bn2g + l * AFL, bn2b + l * AFL);
        k_update_pool<<<N_NODES / PB, 256>>>(ppW, ppb, out, bs);
    }
}